// round 5
// baseline (speedup 1.0000x reference)
#include <cuda_runtime.h>

#define NN 50000
#define NE 800000
#define NRR 8
#define FULLMASK 0xffffffffu

// ---------------- scratch (device globals; no allocations allowed) ----------
__device__ float g_xw[(size_t)NN * NRR * 256];   // per-(node,rel) transformed feats (409.6 MB)
__device__ float g_ssrc[NN * NRR * 4];           // alpha source terms  [n,r,h]
__device__ float g_sdst[NN * NRR * 4];           // alpha dest terms    [n,r,h]
__device__ float g_h[(size_t)NN * 256];          // inter-layer node features
__device__ int   g_deg[NN];
__device__ int   g_rowptr[NN + 1];
__device__ int   g_cursor[NN];
__device__ int   g_srt[NE];                      // edges sorted by dst: src | (rel<<20)
__device__ int   g_flags[2];                     // [0]: edge_index is int64, [1]: edge_type is int64

// ---------------- helpers ---------------------------------------------------
__device__ __forceinline__ int ld_i(const void* p, long long idx, int is64) {
  return is64 ? (int)((const long long*)p)[idx] : ((const int*)p)[idx];
}

// Detect whether index tensors are int64 (high 32-bit words all zero) or int32.
__global__ void k_detect(const unsigned* ei, const unsigned* et) {
  int lane = threadIdx.x & 31;
  if (threadIdx.x < 32) {
    unsigned v = ei[2 * lane + 1] | ei[2 * (lane + 32) + 1];
    unsigned b = __ballot_sync(FULLMASK, v != 0u);
    if (lane == 0) g_flags[0] = (b == 0u) ? 1 : 0;
  } else {
    unsigned v = et[2 * lane + 1] | et[2 * (lane + 32) + 1];
    unsigned b = __ballot_sync(FULLMASK, v != 0u);
    if (lane == 0) g_flags[1] = (b == 0u) ? 1 : 0;
  }
}

__global__ void k_zero_deg() {
  int i = blockIdx.x * blockDim.x + threadIdx.x;
  if (i < NN) g_deg[i] = 0;
}

__global__ void k_hist(const void* ei) {
  int e = blockIdx.x * blockDim.x + threadIdx.x;
  if (e >= NE) return;
  int dst = ld_i(ei, (long long)NE + e, g_flags[0]);
  atomicAdd(&g_deg[dst], 1);
}

// Single-block exclusive scan of g_deg -> g_rowptr (+ cursor copy).
__global__ void k_scan() {
  __shared__ int sh[1024];
  int tid = threadIdx.x;
  int carry = 0;
  for (int base = 0; base < NN; base += 1024) {
    int v = (base + tid < NN) ? g_deg[base + tid] : 0;
    sh[tid] = v;
    __syncthreads();
    for (int off = 1; off < 1024; off <<= 1) {
      int t = (tid >= off) ? sh[tid - off] : 0;
      __syncthreads();
      sh[tid] += t;
      __syncthreads();
    }
    int excl = sh[tid] - v + carry;
    if (base + tid < NN) { g_rowptr[base + tid] = excl; g_cursor[base + tid] = excl; }
    int tot = sh[1023];
    __syncthreads();
    carry += tot;
  }
  if (tid == 0) g_rowptr[NN] = carry;
}

__global__ void k_scatter(const void* ei, const void* et) {
  int e = blockIdx.x * blockDim.x + threadIdx.x;
  if (e >= NE) return;
  int i64e = g_flags[0], i64t = g_flags[1];
  int src = ld_i(ei, e, i64e);
  int dst = ld_i(ei, (long long)NE + e, i64e);
  int r   = ld_i(et, e, i64t);
  int pos = atomicAdd(&g_cursor[dst], 1);
  g_srt[pos] = src | (r << 20);
}

// ---------------- fp32 tiled GEMM: xw[n,r,d] = sum_k A[n,k] * W[r,k,d] ------
// BM=128, BN=64, BK=16, 256 threads, 8x4 microtile. grid=(ceil(M/128), D/64, R)
__global__ __launch_bounds__(256) void k_gemm(const float* __restrict__ Ain,
                                              const float* __restrict__ Wall,
                                              int K, int D) {
  const float* A = Ain ? Ain : g_h;
  __shared__ float As[16][128];
  __shared__ float Bs[16][64];
  int r  = blockIdx.z;
  const float* W = Wall + (size_t)r * K * D;
  int m0 = blockIdx.x * 128, n0 = blockIdx.y * 64;
  int tid = threadIdx.x;
  int ty = tid >> 4, tx = tid & 15;
  int la_r = tid >> 1, la_k = (tid & 1) * 8;
  int lb_k = tid >> 4, lb_d = (tid & 15) * 4;

  float acc[8][4];
#pragma unroll
  for (int i = 0; i < 8; i++)
#pragma unroll
    for (int j = 0; j < 4; j++) acc[i][j] = 0.f;

  for (int k0 = 0; k0 < K; k0 += 16) {
    float4 a0, a1;
    if (m0 + la_r < NN) {
      const float* ap = A + (size_t)(m0 + la_r) * K + k0 + la_k;
      a0 = *(const float4*)ap;
      a1 = *(const float4*)(ap + 4);
    } else {
      a0 = make_float4(0.f, 0.f, 0.f, 0.f);
      a1 = make_float4(0.f, 0.f, 0.f, 0.f);
    }
    float4 b = *(const float4*)(W + (size_t)(k0 + lb_k) * D + n0 + lb_d);
    As[la_k + 0][la_r] = a0.x; As[la_k + 1][la_r] = a0.y;
    As[la_k + 2][la_r] = a0.z; As[la_k + 3][la_r] = a0.w;
    As[la_k + 4][la_r] = a1.x; As[la_k + 5][la_r] = a1.y;
    As[la_k + 6][la_r] = a1.z; As[la_k + 7][la_r] = a1.w;
    *(float4*)&Bs[lb_k][lb_d] = b;
    __syncthreads();
#pragma unroll
    for (int kk = 0; kk < 16; kk++) {
      float ra[8], rb[4];
      *(float4*)&ra[0] = *(const float4*)&As[kk][ty * 8];
      *(float4*)&ra[4] = *(const float4*)&As[kk][ty * 8 + 4];
      *(float4*)&rb[0] = *(const float4*)&Bs[kk][tx * 4];
#pragma unroll
      for (int i = 0; i < 8; i++)
#pragma unroll
        for (int j = 0; j < 4; j++) acc[i][j] = fmaf(ra[i], rb[j], acc[i][j]);
    }
    __syncthreads();
  }
#pragma unroll
  for (int i = 0; i < 8; i++) {
    int m = m0 + ty * 8 + i;
    if (m < NN) {
      float4 o = make_float4(acc[i][0], acc[i][1], acc[i][2], acc[i][3]);
      *(float4*)(g_xw + ((size_t)m * NRR + r) * D + n0 + tx * 4) = o;
    }
  }
}

// ---------------- attention scalar precompute -------------------------------
// H=4, C=64, D=256: warp per (n,r); lane covers 8 channels (all in head lane/8)
__global__ __launch_bounds__(256) void k_srcdst4(const float* __restrict__ asrc,
                                                 const float* __restrict__ adst) {
  int wid = threadIdx.x >> 5, lane = threadIdx.x & 31;
  long long p = (long long)blockIdx.x * 8 + wid;
  if (p >= (long long)NN * NRR) return;
  const float* base = g_xw + (size_t)p * 256;
  float4 x0 = *(const float4*)(base + lane * 8);
  float4 x1 = *(const float4*)(base + lane * 8 + 4);
  float4 s0 = *(const float4*)(asrc + lane * 8);
  float4 s1 = *(const float4*)(asrc + lane * 8 + 4);
  float4 d0 = *(const float4*)(adst + lane * 8);
  float4 d1 = *(const float4*)(adst + lane * 8 + 4);
  float ps = x0.x * s0.x + x0.y * s0.y + x0.z * s0.z + x0.w * s0.w +
             x1.x * s1.x + x1.y * s1.y + x1.z * s1.z + x1.w * s1.w;
  float pd = x0.x * d0.x + x0.y * d0.y + x0.z * d0.z + x0.w * d0.w +
             x1.x * d1.x + x1.y * d1.y + x1.z * d1.z + x1.w * d1.w;
#pragma unroll
  for (int off = 4; off; off >>= 1) {
    ps += __shfl_xor_sync(FULLMASK, ps, off);
    pd += __shfl_xor_sync(FULLMASK, pd, off);
  }
  if ((lane & 7) == 0) {
    g_ssrc[p * 4 + (lane >> 3)] = ps;
    g_sdst[p * 4 + (lane >> 3)] = pd;
  }
}

// H=1, C=64, D=64: warp per (n,r)
__global__ __launch_bounds__(256) void k_srcdst1(const float* __restrict__ asrc,
                                                 const float* __restrict__ adst) {
  int wid = threadIdx.x >> 5, lane = threadIdx.x & 31;
  long long p = (long long)blockIdx.x * 8 + wid;
  if (p >= (long long)NN * NRR) return;
  const float* base = g_xw + (size_t)p * 64;
  float2 x = *(const float2*)(base + lane * 2);
  float2 s = *(const float2*)(asrc + lane * 2);
  float2 d = *(const float2*)(adst + lane * 2);
  float ps = x.x * s.x + x.y * s.y;
  float pd = x.x * d.x + x.y * d.y;
#pragma unroll
  for (int off = 16; off; off >>= 1) {
    ps += __shfl_xor_sync(FULLMASK, ps, off);
    pd += __shfl_xor_sync(FULLMASK, pd, off);
  }
  if (lane == 0) { g_ssrc[p] = ps; g_sdst[p] = pd; }
}

// ---------------- fused attention + aggregate + bias + LN + ELU (H=4) -------
// warp per dst node. CSR edges: no atomics. Writes g_h.
__global__ __launch_bounds__(256) void k_agg4(const float* __restrict__ arel,
                                              const float* __restrict__ bias,
                                              const float* __restrict__ gam,
                                              const float* __restrict__ bet) {
  int wid = threadIdx.x >> 5, lane = threadIdx.x & 31;
  int i = blockIdx.x * 8 + wid;
  if (i >= NN) return;
  float sdv = g_sdst[i * 32 + lane];  // lane l holds sdst[i, l/4, l%4]
  float arv = arel[lane];             // lane l holds arel[l/4, l%4]
  int begin = g_rowptr[i], end = g_rowptr[i + 1];
  int deg = end - begin;
  int nIt = (deg + 31) >> 5;

  float mx0 = -1e30f, mx1 = -1e30f, mx2 = -1e30f, mx3 = -1e30f;
  for (int j = 0; j < nIt; j++) {
    int e = begin + j * 32 + lane;
    bool act = e < end;
    int pk = g_srt[act ? e : begin];
    int src = pk & 0xFFFFF, r = pk >> 20;
    float4 sv = *(const float4*)(g_ssrc + ((size_t)src * 8 + r) * 4);
    float a0 = sv.x + __shfl_sync(FULLMASK, sdv, r * 4 + 0) + __shfl_sync(FULLMASK, arv, r * 4 + 0);
    float a1 = sv.y + __shfl_sync(FULLMASK, sdv, r * 4 + 1) + __shfl_sync(FULLMASK, arv, r * 4 + 1);
    float a2 = sv.z + __shfl_sync(FULLMASK, sdv, r * 4 + 2) + __shfl_sync(FULLMASK, arv, r * 4 + 2);
    float a3 = sv.w + __shfl_sync(FULLMASK, sdv, r * 4 + 3) + __shfl_sync(FULLMASK, arv, r * 4 + 3);
    a0 = a0 > 0.f ? a0 : 0.2f * a0;
    a1 = a1 > 0.f ? a1 : 0.2f * a1;
    a2 = a2 > 0.f ? a2 : 0.2f * a2;
    a3 = a3 > 0.f ? a3 : 0.2f * a3;
    if (act) {
      mx0 = fmaxf(mx0, a0); mx1 = fmaxf(mx1, a1);
      mx2 = fmaxf(mx2, a2); mx3 = fmaxf(mx3, a3);
    }
  }
#pragma unroll
  for (int off = 16; off; off >>= 1) {
    mx0 = fmaxf(mx0, __shfl_xor_sync(FULLMASK, mx0, off));
    mx1 = fmaxf(mx1, __shfl_xor_sync(FULLMASK, mx1, off));
    mx2 = fmaxf(mx2, __shfl_xor_sync(FULLMASK, mx2, off));
    mx3 = fmaxf(mx3, __shfl_xor_sync(FULLMASK, mx3, off));
  }

  float dn0 = 0.f, dn1 = 0.f, dn2 = 0.f, dn3 = 0.f;
  for (int j = 0; j < nIt; j++) {
    int e = begin + j * 32 + lane;
    bool act = e < end;
    int pk = g_srt[act ? e : begin];
    int src = pk & 0xFFFFF, r = pk >> 20;
    float4 sv = *(const float4*)(g_ssrc + ((size_t)src * 8 + r) * 4);
    float a0 = sv.x + __shfl_sync(FULLMASK, sdv, r * 4 + 0) + __shfl_sync(FULLMASK, arv, r * 4 + 0);
    float a1 = sv.y + __shfl_sync(FULLMASK, sdv, r * 4 + 1) + __shfl_sync(FULLMASK, arv, r * 4 + 1);
    float a2 = sv.z + __shfl_sync(FULLMASK, sdv, r * 4 + 2) + __shfl_sync(FULLMASK, arv, r * 4 + 2);
    float a3 = sv.w + __shfl_sync(FULLMASK, sdv, r * 4 + 3) + __shfl_sync(FULLMASK, arv, r * 4 + 3);
    a0 = a0 > 0.f ? a0 : 0.2f * a0;
    a1 = a1 > 0.f ? a1 : 0.2f * a1;
    a2 = a2 > 0.f ? a2 : 0.2f * a2;
    a3 = a3 > 0.f ? a3 : 0.2f * a3;
    if (act) {
      dn0 += __expf(a0 - mx0); dn1 += __expf(a1 - mx1);
      dn2 += __expf(a2 - mx2); dn3 += __expf(a3 - mx3);
    }
  }
#pragma unroll
  for (int off = 16; off; off >>= 1) {
    dn0 += __shfl_xor_sync(FULLMASK, dn0, off);
    dn1 += __shfl_xor_sync(FULLMASK, dn1, off);
    dn2 += __shfl_xor_sync(FULLMASK, dn2, off);
    dn3 += __shfl_xor_sync(FULLMASK, dn3, off);
  }
  float iv0 = 1.f / dn0, iv1 = 1.f / dn1, iv2 = 1.f / dn2, iv3 = 1.f / dn3;

  float acc0 = 0.f, acc1 = 0.f, acc2 = 0.f, acc3 = 0.f;
  float acc4 = 0.f, acc5 = 0.f, acc6 = 0.f, acc7 = 0.f;
  int h = lane >> 3;
  for (int e = begin; e < end; e++) {
    int pk = g_srt[e];
    int src = pk & 0xFFFFF, r = pk >> 20;
    float4 sv = *(const float4*)(g_ssrc + ((size_t)src * 8 + r) * 4);
    float a0 = sv.x + __shfl_sync(FULLMASK, sdv, r * 4 + 0) + __shfl_sync(FULLMASK, arv, r * 4 + 0);
    float a1 = sv.y + __shfl_sync(FULLMASK, sdv, r * 4 + 1) + __shfl_sync(FULLMASK, arv, r * 4 + 1);
    float a2 = sv.z + __shfl_sync(FULLMASK, sdv, r * 4 + 2) + __shfl_sync(FULLMASK, arv, r * 4 + 2);
    float a3 = sv.w + __shfl_sync(FULLMASK, sdv, r * 4 + 3) + __shfl_sync(FULLMASK, arv, r * 4 + 3);
    a0 = a0 > 0.f ? a0 : 0.2f * a0;
    a1 = a1 > 0.f ? a1 : 0.2f * a1;
    a2 = a2 > 0.f ? a2 : 0.2f * a2;
    a3 = a3 > 0.f ? a3 : 0.2f * a3;
    float c0 = __expf(a0 - mx0) * iv0;
    float c1 = __expf(a1 - mx1) * iv1;
    float c2 = __expf(a2 - mx2) * iv2;
    float c3 = __expf(a3 - mx3) * iv3;
    float c = (h == 0) ? c0 : (h == 1) ? c1 : (h == 2) ? c2 : c3;
    const float* xp = g_xw + ((size_t)src * 8 + r) * 256 + lane * 8;
    float4 v0 = *(const float4*)xp;
    float4 v1 = *(const float4*)(xp + 4);
    acc0 = fmaf(c, v0.x, acc0); acc1 = fmaf(c, v0.y, acc1);
    acc2 = fmaf(c, v0.z, acc2); acc3 = fmaf(c, v0.w, acc3);
    acc4 = fmaf(c, v1.x, acc4); acc5 = fmaf(c, v1.y, acc5);
    acc6 = fmaf(c, v1.z, acc6); acc7 = fmaf(c, v1.w, acc7);
  }

  // bias + LayerNorm + ELU, row is resident across the warp (8 vals/lane)
  float4 b0 = *(const float4*)(bias + lane * 8);
  float4 b1 = *(const float4*)(bias + lane * 8 + 4);
  float w0 = acc0 + b0.x, w1 = acc1 + b0.y, w2 = acc2 + b0.z, w3 = acc3 + b0.w;
  float w4 = acc4 + b1.x, w5 = acc5 + b1.y, w6 = acc6 + b1.z, w7 = acc7 + b1.w;
  float s  = w0 + w1 + w2 + w3 + w4 + w5 + w6 + w7;
  float ss = w0 * w0 + w1 * w1 + w2 * w2 + w3 * w3 + w4 * w4 + w5 * w5 + w6 * w6 + w7 * w7;
#pragma unroll
  for (int off = 16; off; off >>= 1) {
    s  += __shfl_xor_sync(FULLMASK, s, off);
    ss += __shfl_xor_sync(FULLMASK, ss, off);
  }
  float mean = s * (1.f / 256.f);
  float var  = fmaxf(ss * (1.f / 256.f) - mean * mean, 0.f);
  float inv  = rsqrtf(var + 1e-5f);
  float4 gg0 = *(const float4*)(gam + lane * 8);
  float4 gg1 = *(const float4*)(gam + lane * 8 + 4);
  float4 bb0 = *(const float4*)(bet + lane * 8);
  float4 bb1 = *(const float4*)(bet + lane * 8 + 4);
  float o0 = (w0 - mean) * inv * gg0.x + bb0.x;
  float o1 = (w1 - mean) * inv * gg0.y + bb0.y;
  float o2 = (w2 - mean) * inv * gg0.z + bb0.z;
  float o3 = (w3 - mean) * inv * gg0.w + bb0.w;
  float o4 = (w4 - mean) * inv * gg1.x + bb1.x;
  float o5 = (w5 - mean) * inv * gg1.y + bb1.y;
  float o6 = (w6 - mean) * inv * gg1.z + bb1.z;
  float o7 = (w7 - mean) * inv * gg1.w + bb1.w;
  o0 = o0 > 0.f ? o0 : expm1f(o0);
  o1 = o1 > 0.f ? o1 : expm1f(o1);
  o2 = o2 > 0.f ? o2 : expm1f(o2);
  o3 = o3 > 0.f ? o3 : expm1f(o3);
  o4 = o4 > 0.f ? o4 : expm1f(o4);
  o5 = o5 > 0.f ? o5 : expm1f(o5);
  o6 = o6 > 0.f ? o6 : expm1f(o6);
  o7 = o7 > 0.f ? o7 : expm1f(o7);
  float* op = g_h + (size_t)i * 256 + lane * 8;
  *(float4*)op       = make_float4(o0, o1, o2, o3);
  *(float4*)(op + 4) = make_float4(o4, o5, o6, o7);
}

// ---------------- final layer: H=1, D=64, no LN/ELU, writes d_out -----------
__global__ __launch_bounds__(256) void k_agg1(const float* __restrict__ arel,
                                              const float* __restrict__ bias,
                                              float* __restrict__ out) {
  int wid = threadIdx.x >> 5, lane = threadIdx.x & 31;
  int i = blockIdx.x * 8 + wid;
  if (i >= NN) return;
  float sdv = (lane < 8) ? g_sdst[i * 8 + lane] : 0.f;
  float arv = (lane < 8) ? arel[lane] : 0.f;
  int begin = g_rowptr[i], end = g_rowptr[i + 1];
  int deg = end - begin;
  int nIt = (deg + 31) >> 5;

  float mx = -1e30f;
  for (int j = 0; j < nIt; j++) {
    int e = begin + j * 32 + lane;
    bool act = e < end;
    int pk = g_srt[act ? e : begin];
    int src = pk & 0xFFFFF, r = pk >> 20;
    float a = g_ssrc[(size_t)src * 8 + r] + __shfl_sync(FULLMASK, sdv, r) + __shfl_sync(FULLMASK, arv, r);
    a = a > 0.f ? a : 0.2f * a;
    if (act) mx = fmaxf(mx, a);
  }
#pragma unroll
  for (int off = 16; off; off >>= 1) mx = fmaxf(mx, __shfl_xor_sync(FULLMASK, mx, off));

  float dn = 0.f;
  for (int j = 0; j < nIt; j++) {
    int e = begin + j * 32 + lane;
    bool act = e < end;
    int pk = g_srt[act ? e : begin];
    int src = pk & 0xFFFFF, r = pk >> 20;
    float a = g_ssrc[(size_t)src * 8 + r] + __shfl_sync(FULLMASK, sdv, r) + __shfl_sync(FULLMASK, arv, r);
    a = a > 0.f ? a : 0.2f * a;
    if (act) dn += __expf(a - mx);
  }
#pragma unroll
  for (int off = 16; off; off >>= 1) dn += __shfl_xor_sync(FULLMASK, dn, off);
  float iv = 1.f / dn;

  float a0 = 0.f, a1 = 0.f;
  for (int e = begin; e < end; e++) {
    int pk = g_srt[e];
    int src = pk & 0xFFFFF, r = pk >> 20;
    float a = g_ssrc[(size_t)src * 8 + r] + __shfl_sync(FULLMASK, sdv, r) + __shfl_sync(FULLMASK, arv, r);
    a = a > 0.f ? a : 0.2f * a;
    float c = __expf(a - mx) * iv;
    float2 vv = *(const float2*)(g_xw + ((size_t)src * 8 + r) * 64 + lane * 2);
    a0 = fmaf(c, vv.x, a0);
    a1 = fmaf(c, vv.y, a1);
  }
  out[(size_t)i * 64 + lane * 2]     = a0 + bias[lane * 2];
  out[(size_t)i * 64 + lane * 2 + 1] = a1 + bias[lane * 2 + 1];
}

// ---------------- launch -----------------------------------------------------
extern "C" void kernel_launch(void* const* d_in, const int* in_sizes, int n_in,
                              void* d_out, int out_size) {
  const float* x   = (const float*)d_in[0];
  const void*  ei  = d_in[1];
  const void*  et  = d_in[2];
  const float* W0  = (const float*)d_in[3];
  const float* as0 = (const float*)d_in[4];
  const float* ad0 = (const float*)d_in[5];
  const float* ar0 = (const float*)d_in[6];
  const float* bi0 = (const float*)d_in[7];
  const float* W1  = (const float*)d_in[8];
  const float* as1 = (const float*)d_in[9];
  const float* ad1 = (const float*)d_in[10];
  const float* ar1 = (const float*)d_in[11];
  const float* bi1 = (const float*)d_in[12];
  const float* W2  = (const float*)d_in[13];
  const float* as2 = (const float*)d_in[14];
  const float* ad2 = (const float*)d_in[15];
  const float* ar2 = (const float*)d_in[16];
  const float* bi2 = (const float*)d_in[17];
  const float* g0  = (const float*)d_in[18];
  const float* be0 = (const float*)d_in[19];
  const float* g1  = (const float*)d_in[20];
  const float* be1 = (const float*)d_in[21];
  float* out = (float*)d_out;

  // graph prep (edge list is static across layers)
  k_detect<<<1, 64>>>((const unsigned*)ei, (const unsigned*)et);
  k_zero_deg<<<(NN + 255) / 256, 256>>>();
  k_hist<<<(NE + 255) / 256, 256>>>(ei);
  k_scan<<<1, 1024>>>();
  k_scatter<<<(NE + 255) / 256, 256>>>(ei, et);

  const int MB = (NN + 127) / 128;  // 391

  // layer 0: in=128 -> [N,8,256]
  k_gemm<<<dim3(MB, 4, 8), 256>>>(x, W0, 128, 256);
  k_srcdst4<<<(NN * NRR + 7) / 8, 256>>>(as0, ad0);
  k_agg4<<<(NN + 7) / 8, 256>>>(ar0, bi0, g0, be0);

  // layer 1: in=256 -> [N,8,256]
  k_gemm<<<dim3(MB, 4, 8), 256>>>(nullptr, W1, 256, 256);
  k_srcdst4<<<(NN * NRR + 7) / 8, 256>>>(as1, ad1);
  k_agg4<<<(NN + 7) / 8, 256>>>(ar1, bi1, g1, be1);

  // layer 2: in=256 -> [N,8,64], H=1, writes output
  k_gemm<<<dim3(MB, 1, 8), 256>>>(nullptr, W2, 256, 64);
  k_srcdst1<<<(NN * NRR + 7) / 8, 256>>>(as2, ad2);
  k_agg1<<<(NN + 7) / 8, 256>>>(ar2, bi2, out);
}

// round 8
// speedup vs baseline: 1.1559x; 1.1559x over previous
#include <cuda_runtime.h>
#include <cuda_bf16.h>
#include <cstdint>

#define NN 50000
#define NE 800000
#define NRR 8
#define FULLMASK 0xffffffffu

// ---------------- scratch (device globals; no allocations allowed) ----------
__device__ float g_xw[(size_t)NN * NRR * 256];   // per-(node,rel) transformed feats
__device__ float g_ssrc[NN * NRR * 4];           // alpha source terms  [n,r,h]
__device__ float g_sdst[NN * NRR * 4];           // alpha dest terms    [n,r,h]
__device__ float g_h[(size_t)NN * 256];          // inter-layer node features
__device__ int   g_deg[NN];
__device__ int   g_rowptr[NN + 1];
__device__ int   g_cursor[NN];
__device__ int   g_srt[NE];                      // edges sorted by dst: src | (rel<<20)
__device__ int   g_flags[2];

// ---------------- helpers ---------------------------------------------------
__device__ __forceinline__ int ld_i(const void* p, long long idx, int is64) {
  return is64 ? (int)((const long long*)p)[idx] : ((const int*)p)[idx];
}

__global__ void k_detect(const unsigned* ei, const unsigned* et) {
  int lane = threadIdx.x & 31;
  if (threadIdx.x < 32) {
    unsigned v = ei[2 * lane + 1] | ei[2 * (lane + 32) + 1];
    unsigned b = __ballot_sync(FULLMASK, v != 0u);
    if (lane == 0) g_flags[0] = (b == 0u) ? 1 : 0;
  } else {
    unsigned v = et[2 * lane + 1] | et[2 * (lane + 32) + 1];
    unsigned b = __ballot_sync(FULLMASK, v != 0u);
    if (lane == 0) g_flags[1] = (b == 0u) ? 1 : 0;
  }
}

__global__ void k_zero_deg() {
  int i = blockIdx.x * blockDim.x + threadIdx.x;
  if (i < NN) g_deg[i] = 0;
}

__global__ void k_hist(const void* ei) {
  int e = blockIdx.x * blockDim.x + threadIdx.x;
  if (e >= NE) return;
  int dst = ld_i(ei, (long long)NE + e, g_flags[0]);
  atomicAdd(&g_deg[dst], 1);
}

// Chunk-per-thread single-block scan.
__global__ void k_scan2() {
  __shared__ int wsum[32];
  const int CH = (NN + 1023) / 1024;  // 49
  int tid = threadIdx.x, lane = tid & 31, w = tid >> 5;
  int b0 = tid * CH, b1 = min(b0 + CH, NN);
  int s = 0;
  for (int i = b0; i < b1; i++) s += g_deg[i];
  int v = s;
#pragma unroll
  for (int off = 1; off < 32; off <<= 1) {
    int t = __shfl_up_sync(FULLMASK, v, off);
    if (lane >= off) v += t;
  }
  if (lane == 31) wsum[w] = v;
  __syncthreads();
  if (w == 0) {
    int t = wsum[lane];
#pragma unroll
    for (int off = 1; off < 32; off <<= 1) {
      int u = __shfl_up_sync(FULLMASK, t, off);
      if (lane >= off) t += u;
    }
    wsum[lane] = t;
  }
  __syncthreads();
  int run = (v - s) + (w > 0 ? wsum[w - 1] : 0);
  for (int i = b0; i < b1; i++) {
    g_rowptr[i] = run; g_cursor[i] = run;
    run += g_deg[i];
  }
  if (tid == 1023) g_rowptr[NN] = run;
}

__global__ void k_scatter(const void* ei, const void* et) {
  int e = blockIdx.x * blockDim.x + threadIdx.x;
  if (e >= NE) return;
  int i64e = g_flags[0], i64t = g_flags[1];
  int src = ld_i(ei, e, i64e);
  int dst = ld_i(ei, (long long)NE + e, i64e);
  int r   = ld_i(et, e, i64t);
  int pos = atomicAdd(&g_cursor[dst], 1);
  g_srt[pos] = src | (r << 20);
}

// ---------------- tensor-core GEMM (bf16 split, ~fp32 accuracy) -------------
// xw[n, r*D + d] = sum_k A[n,k] * W[r,k,d]
// A = Ahi + Alo (bf16 each); W likewise. C = AhiWhi + AhiWlo + AloWhi (fp32 acc).
// BM=128, BN=64, BK=16. 256 thr = 8 warps as 4(m) x 2(n); warp tile 32x32.
#define MMA_BF16(d, a, b)                                                     \
  asm volatile(                                                               \
      "mma.sync.aligned.m16n8k16.row.col.f32.bf16.bf16.f32 "                  \
      "{%0,%1,%2,%3},{%4,%5,%6,%7},{%8,%9},{%0,%1,%2,%3};"                    \
      : "+f"((d)[0]), "+f"((d)[1]), "+f"((d)[2]), "+f"((d)[3])                \
      : "r"((a)[0]), "r"((a)[1]), "r"((a)[2]), "r"((a)[3]),                   \
        "r"((b)[0]), "r"((b)[1]))

#define LDSM_X4(a, addr)                                                      \
  asm volatile("ldmatrix.sync.aligned.m8n8.x4.shared.b16 {%0,%1,%2,%3},[%4];" \
               : "=r"((a)[0]), "=r"((a)[1]), "=r"((a)[2]), "=r"((a)[3])       \
               : "r"(addr))

#define LDSM_X2T(b, addr)                                                     \
  asm volatile("ldmatrix.sync.aligned.m8n8.x2.trans.shared.b16 {%0,%1},[%2];" \
               : "=r"((b)[0]), "=r"((b)[1]) : "r"(addr))

__device__ __forceinline__ void split_bf16(float v, __nv_bfloat16& hi, __nv_bfloat16& lo) {
  hi = __float2bfloat16(v);
  lo = __float2bfloat16(v - __bfloat162float(hi));
}

__global__ __launch_bounds__(256) void k_gemm_tc(const float* __restrict__ Ain,
                                                 const float* __restrict__ Wall,
                                                 int K, int D) {
  const float* A = Ain ? Ain : g_h;
  __shared__ __nv_bfloat16 As_h[128][24];   // padded stride: conflict-free ldmatrix
  __shared__ __nv_bfloat16 As_l[128][24];
  __shared__ __nv_bfloat16 Bs_h[16][72];
  __shared__ __nv_bfloat16 Bs_l[16][72];

  int r = blockIdx.z;
  const float* W = Wall + (size_t)r * K * D;
  int m0 = blockIdx.x * 128, n0 = blockIdx.y * 64;
  int tid = threadIdx.x, lane = tid & 31, wid = tid >> 5;
  int warp_m = wid >> 1, warp_n = wid & 1;

  // loader indices
  int la_r = tid >> 1, la_c = (tid & 1) * 8;       // A: row 0..127, col 0/8
  int lb_r = tid >> 4, lb_c = (tid & 15) * 4;      // B: row 0..15, col 0..60

  // ldmatrix source addresses are k-tile-invariant: precompute
  int alr = lane & 15, alc = (lane >> 4) * 8;
  uint32_t aah[2], aal[2], bah[4], bal[4];
#pragma unroll
  for (int mi = 0; mi < 2; mi++) {
    int row = warp_m * 32 + mi * 16 + alr;
    aah[mi] = (uint32_t)__cvta_generic_to_shared(&As_h[row][alc]);
    aal[mi] = (uint32_t)__cvta_generic_to_shared(&As_l[row][alc]);
  }
#pragma unroll
  for (int ni = 0; ni < 4; ni++) {
    int col = warp_n * 32 + ni * 8;
    bah[ni] = (uint32_t)__cvta_generic_to_shared(&Bs_h[lane & 15][col]);
    bal[ni] = (uint32_t)__cvta_generic_to_shared(&Bs_l[lane & 15][col]);
  }

  float acc[2][4][4];
#pragma unroll
  for (int mi = 0; mi < 2; mi++)
#pragma unroll
    for (int ni = 0; ni < 4; ni++)
#pragma unroll
      for (int q = 0; q < 4; q++) acc[mi][ni][q] = 0.f;

  for (int k0 = 0; k0 < K; k0 += 16) {
    // load + split A tile (128x16)
    float av[8];
    if (m0 + la_r < NN) {
      const float* ap = A + (size_t)(m0 + la_r) * K + k0 + la_c;
      *(float4*)&av[0] = *(const float4*)ap;
      *(float4*)&av[4] = *(const float4*)(ap + 4);
    } else {
#pragma unroll
      for (int j = 0; j < 8; j++) av[j] = 0.f;
    }
#pragma unroll
    for (int j = 0; j < 8; j++) {
      __nv_bfloat16 h, l;
      split_bf16(av[j], h, l);
      As_h[la_r][la_c + j] = h;
      As_l[la_r][la_c + j] = l;
    }
    // load + split B tile (16x64)
    float4 bv = *(const float4*)(W + (size_t)(k0 + lb_r) * D + n0 + lb_c);
    {
      __nv_bfloat16 h, l;
      split_bf16(bv.x, h, l); Bs_h[lb_r][lb_c + 0] = h; Bs_l[lb_r][lb_c + 0] = l;
      split_bf16(bv.y, h, l); Bs_h[lb_r][lb_c + 1] = h; Bs_l[lb_r][lb_c + 1] = l;
      split_bf16(bv.z, h, l); Bs_h[lb_r][lb_c + 2] = h; Bs_l[lb_r][lb_c + 2] = l;
      split_bf16(bv.w, h, l); Bs_h[lb_r][lb_c + 3] = h; Bs_l[lb_r][lb_c + 3] = l;
    }
    __syncthreads();

    uint32_t ah[2][4], al[2][4], bh[4][2], bl[4][2];
#pragma unroll
    for (int mi = 0; mi < 2; mi++) { LDSM_X4(ah[mi], aah[mi]); LDSM_X4(al[mi], aal[mi]); }
#pragma unroll
    for (int ni = 0; ni < 4; ni++) { LDSM_X2T(bh[ni], bah[ni]); LDSM_X2T(bl[ni], bal[ni]); }

#pragma unroll
    for (int mi = 0; mi < 2; mi++)
#pragma unroll
      for (int ni = 0; ni < 4; ni++) {
        MMA_BF16(acc[mi][ni], ah[mi], bh[ni]);
        MMA_BF16(acc[mi][ni], ah[mi], bl[ni]);
        MMA_BF16(acc[mi][ni], al[mi], bh[ni]);
      }
    __syncthreads();
  }

  // epilogue: frag layout m16n8 -> rows lane>>2 (+8), cols (lane&3)*2 (+1)
  size_t rowstride = (size_t)NRR * D;
  float* outbase = g_xw + (size_t)r * D + n0;
#pragma unroll
  for (int mi = 0; mi < 2; mi++) {
    int mrow = m0 + warp_m * 32 + mi * 16 + (lane >> 2);
#pragma unroll
    for (int ni = 0; ni < 4; ni++) {
      int col = warp_n * 32 + ni * 8 + (lane & 3) * 2;
      if (mrow < NN)
        *(float2*)(outbase + (size_t)mrow * rowstride + col) =
            make_float2(acc[mi][ni][0], acc[mi][ni][1]);
      if (mrow + 8 < NN)
        *(float2*)(outbase + (size_t)(mrow + 8) * rowstride + col) =
            make_float2(acc[mi][ni][2], acc[mi][ni][3]);
    }
  }
}

// ---------------- attention scalar precompute -------------------------------
__global__ __launch_bounds__(256) void k_srcdst4(const float* __restrict__ asrc,
                                                 const float* __restrict__ adst) {
  int wid = threadIdx.x >> 5, lane = threadIdx.x & 31;
  long long p = (long long)blockIdx.x * 8 + wid;
  if (p >= (long long)NN * NRR) return;
  const float* base = g_xw + (size_t)p * 256;
  float4 x0 = *(const float4*)(base + lane * 8);
  float4 x1 = *(const float4*)(base + lane * 8 + 4);
  float4 s0 = *(const float4*)(asrc + lane * 8);
  float4 s1 = *(const float4*)(asrc + lane * 8 + 4);
  float4 d0 = *(const float4*)(adst + lane * 8);
  float4 d1 = *(const float4*)(adst + lane * 8 + 4);
  float ps = x0.x * s0.x + x0.y * s0.y + x0.z * s0.z + x0.w * s0.w +
             x1.x * s1.x + x1.y * s1.y + x1.z * s1.z + x1.w * s1.w;
  float pd = x0.x * d0.x + x0.y * d0.y + x0.z * d0.z + x0.w * d0.w +
             x1.x * d1.x + x1.y * d1.y + x1.z * d1.z + x1.w * d1.w;
#pragma unroll
  for (int off = 4; off; off >>= 1) {
    ps += __shfl_xor_sync(FULLMASK, ps, off);
    pd += __shfl_xor_sync(FULLMASK, pd, off);
  }
  if ((lane & 7) == 0) {
    g_ssrc[p * 4 + (lane >> 3)] = ps;
    g_sdst[p * 4 + (lane >> 3)] = pd;
  }
}

__global__ __launch_bounds__(256) void k_srcdst1(const float* __restrict__ asrc,
                                                 const float* __restrict__ adst) {
  int wid = threadIdx.x >> 5, lane = threadIdx.x & 31;
  long long p = (long long)blockIdx.x * 8 + wid;
  if (p >= (long long)NN * NRR) return;
  const float* base = g_xw + (size_t)p * 64;
  float2 x = *(const float2*)(base + lane * 2);
  float2 s = *(const float2*)(asrc + lane * 2);
  float2 d = *(const float2*)(adst + lane * 2);
  float ps = x.x * s.x + x.y * s.y;
  float pd = x.x * d.x + x.y * d.y;
#pragma unroll
  for (int off = 16; off; off >>= 1) {
    ps += __shfl_xor_sync(FULLMASK, ps, off);
    pd += __shfl_xor_sync(FULLMASK, pd, off);
  }
  if (lane == 0) { g_ssrc[p] = ps; g_sdst[p] = pd; }
}

// ---------------- fused attention + aggregate + bias + LN + ELU (H=4) -------
__global__ __launch_bounds__(256) void k_agg4(const float* __restrict__ arel,
                                              const float* __restrict__ bias,
                                              const float* __restrict__ gam,
                                              const float* __restrict__ bet) {
  int wid = threadIdx.x >> 5, lane = threadIdx.x & 31;
  int i = blockIdx.x * 8 + wid;
  if (i >= NN) return;
  float sdv = g_sdst[i * 32 + lane];
  float arv = arel[lane];
  int begin = g_rowptr[i], end = g_rowptr[i + 1];
  int deg = end - begin;
  int nIt = (deg + 31) >> 5;

  float mx0 = -1e30f, mx1 = -1e30f, mx2 = -1e30f, mx3 = -1e30f;
  for (int j = 0; j < nIt; j++) {
    int e = begin + j * 32 + lane;
    bool act = e < end;
    int pk = g_srt[act ? e : begin];
    int src = pk & 0xFFFFF, r = pk >> 20;
    float4 sv = *(const float4*)(g_ssrc + ((size_t)src * 8 + r) * 4);
    float a0 = sv.x + __shfl_sync(FULLMASK, sdv, r * 4 + 0) + __shfl_sync(FULLMASK, arv, r * 4 + 0);
    float a1 = sv.y + __shfl_sync(FULLMASK, sdv, r * 4 + 1) + __shfl_sync(FULLMASK, arv, r * 4 + 1);
    float a2 = sv.z + __shfl_sync(FULLMASK, sdv, r * 4 + 2) + __shfl_sync(FULLMASK, arv, r * 4 + 2);
    float a3 = sv.w + __shfl_sync(FULLMASK, sdv, r * 4 + 3) + __shfl_sync(FULLMASK, arv, r * 4 + 3);
    a0 = a0 > 0.f ? a0 : 0.2f * a0;
    a1 = a1 > 0.f ? a1 : 0.2f * a1;
    a2 = a2 > 0.f ? a2 : 0.2f * a2;
    a3 = a3 > 0.f ? a3 : 0.2f * a3;
    if (act) {
      mx0 = fmaxf(mx0, a0); mx1 = fmaxf(mx1, a1);
      mx2 = fmaxf(mx2, a2); mx3 = fmaxf(mx3, a3);
    }
  }
#pragma unroll
  for (int off = 16; off; off >>= 1) {
    mx0 = fmaxf(mx0, __shfl_xor_sync(FULLMASK, mx0, off));
    mx1 = fmaxf(mx1, __shfl_xor_sync(FULLMASK, mx1, off));
    mx2 = fmaxf(mx2, __shfl_xor_sync(FULLMASK, mx2, off));
    mx3 = fmaxf(mx3, __shfl_xor_sync(FULLMASK, mx3, off));
  }

  float dn0 = 0.f, dn1 = 0.f, dn2 = 0.f, dn3 = 0.f;
  for (int j = 0; j < nIt; j++) {
    int e = begin + j * 32 + lane;
    bool act = e < end;
    int pk = g_srt[act ? e : begin];
    int src = pk & 0xFFFFF, r = pk >> 20;
    float4 sv = *(const float4*)(g_ssrc + ((size_t)src * 8 + r) * 4);
    float a0 = sv.x + __shfl_sync(FULLMASK, sdv, r * 4 + 0) + __shfl_sync(FULLMASK, arv, r * 4 + 0);
    float a1 = sv.y + __shfl_sync(FULLMASK, sdv, r * 4 + 1) + __shfl_sync(FULLMASK, arv, r * 4 + 1);
    float a2 = sv.z + __shfl_sync(FULLMASK, sdv, r * 4 + 2) + __shfl_sync(FULLMASK, arv, r * 4 + 2);
    float a3 = sv.w + __shfl_sync(FULLMASK, sdv, r * 4 + 3) + __shfl_sync(FULLMASK, arv, r * 4 + 3);
    a0 = a0 > 0.f ? a0 : 0.2f * a0;
    a1 = a1 > 0.f ? a1 : 0.2f * a1;
    a2 = a2 > 0.f ? a2 : 0.2f * a2;
    a3 = a3 > 0.f ? a3 : 0.2f * a3;
    if (act) {
      dn0 += __expf(a0 - mx0); dn1 += __expf(a1 - mx1);
      dn2 += __expf(a2 - mx2); dn3 += __expf(a3 - mx3);
    }
  }
#pragma unroll
  for (int off = 16; off; off >>= 1) {
    dn0 += __shfl_xor_sync(FULLMASK, dn0, off);
    dn1 += __shfl_xor_sync(FULLMASK, dn1, off);
    dn2 += __shfl_xor_sync(FULLMASK, dn2, off);
    dn3 += __shfl_xor_sync(FULLMASK, dn3, off);
  }
  float iv0 = 1.f / dn0, iv1 = 1.f / dn1, iv2 = 1.f / dn2, iv3 = 1.f / dn3;

  float acc0 = 0.f, acc1 = 0.f, acc2 = 0.f, acc3 = 0.f;
  float acc4 = 0.f, acc5 = 0.f, acc6 = 0.f, acc7 = 0.f;
  int h = lane >> 3;
  for (int e = begin; e < end; e++) {
    int pk = g_srt[e];
    int src = pk & 0xFFFFF, r = pk >> 20;
    float4 sv = *(const float4*)(g_ssrc + ((size_t)src * 8 + r) * 4);
    float a0 = sv.x + __shfl_sync(FULLMASK, sdv, r * 4 + 0) + __shfl_sync(FULLMASK, arv, r * 4 + 0);
    float a1 = sv.y + __shfl_sync(FULLMASK, sdv, r * 4 + 1) + __shfl_sync(FULLMASK, arv, r * 4 + 1);
    float a2 = sv.z + __shfl_sync(FULLMASK, sdv, r * 4 + 2) + __shfl_sync(FULLMASK, arv, r * 4 + 2);
    float a3 = sv.w + __shfl_sync(FULLMASK, sdv, r * 4 + 3) + __shfl_sync(FULLMASK, arv, r * 4 + 3);
    a0 = a0 > 0.f ? a0 : 0.2f * a0;
    a1 = a1 > 0.f ? a1 : 0.2f * a1;
    a2 = a2 > 0.f ? a2 : 0.2f * a2;
    a3 = a3 > 0.f ? a3 : 0.2f * a3;
    float c0 = __expf(a0 - mx0) * iv0;
    float c1 = __expf(a1 - mx1) * iv1;
    float c2 = __expf(a2 - mx2) * iv2;
    float c3 = __expf(a3 - mx3) * iv3;
    float c = (h == 0) ? c0 : (h == 1) ? c1 : (h == 2) ? c2 : c3;
    const float* xp = g_xw + ((size_t)src * 8 + r) * 256 + lane * 8;
    float4 v0 = *(const float4*)xp;
    float4 v1 = *(const float4*)(xp + 4);
    acc0 = fmaf(c, v0.x, acc0); acc1 = fmaf(c, v0.y, acc1);
    acc2 = fmaf(c, v0.z, acc2); acc3 = fmaf(c, v0.w, acc3);
    acc4 = fmaf(c, v1.x, acc4); acc5 = fmaf(c, v1.y, acc5);
    acc6 = fmaf(c, v1.z, acc6); acc7 = fmaf(c, v1.w, acc7);
  }

  float4 b0 = *(const float4*)(bias + lane * 8);
  float4 b1 = *(const float4*)(bias + lane * 8 + 4);
  float w0 = acc0 + b0.x, w1 = acc1 + b0.y, w2 = acc2 + b0.z, w3 = acc3 + b0.w;
  float w4 = acc4 + b1.x, w5 = acc5 + b1.y, w6 = acc6 + b1.z, w7 = acc7 + b1.w;
  float s  = w0 + w1 + w2 + w3 + w4 + w5 + w6 + w7;
  float ss = w0 * w0 + w1 * w1 + w2 * w2 + w3 * w3 + w4 * w4 + w5 * w5 + w6 * w6 + w7 * w7;
#pragma unroll
  for (int off = 16; off; off >>= 1) {
    s  += __shfl_xor_sync(FULLMASK, s, off);
    ss += __shfl_xor_sync(FULLMASK, ss, off);
  }
  float mean = s * (1.f / 256.f);
  float var  = fmaxf(ss * (1.f / 256.f) - mean * mean, 0.f);
  float inv  = rsqrtf(var + 1e-5f);
  float4 gg0 = *(const float4*)(gam + lane * 8);
  float4 gg1 = *(const float4*)(gam + lane * 8 + 4);
  float4 bb0 = *(const float4*)(bet + lane * 8);
  float4 bb1 = *(const float4*)(bet + lane * 8 + 4);
  float o0 = (w0 - mean) * inv * gg0.x + bb0.x;
  float o1 = (w1 - mean) * inv * gg0.y + bb0.y;
  float o2 = (w2 - mean) * inv * gg0.z + bb0.z;
  float o3 = (w3 - mean) * inv * gg0.w + bb0.w;
  float o4 = (w4 - mean) * inv * gg1.x + bb1.x;
  float o5 = (w5 - mean) * inv * gg1.y + bb1.y;
  float o6 = (w6 - mean) * inv * gg1.z + bb1.z;
  float o7 = (w7 - mean) * inv * gg1.w + bb1.w;
  o0 = o0 > 0.f ? o0 : expm1f(o0);
  o1 = o1 > 0.f ? o1 : expm1f(o1);
  o2 = o2 > 0.f ? o2 : expm1f(o2);
  o3 = o3 > 0.f ? o3 : expm1f(o3);
  o4 = o4 > 0.f ? o4 : expm1f(o4);
  o5 = o5 > 0.f ? o5 : expm1f(o5);
  o6 = o6 > 0.f ? o6 : expm1f(o6);
  o7 = o7 > 0.f ? o7 : expm1f(o7);
  float* op = g_h + (size_t)i * 256 + lane * 8;
  *(float4*)op       = make_float4(o0, o1, o2, o3);
  *(float4*)(op + 4) = make_float4(o4, o5, o6, o7);
}

// ---------------- final layer: H=1, D=64, writes d_out ----------------------
__global__ __launch_bounds__(256) void k_agg1(const float* __restrict__ arel,
                                              const float* __restrict__ bias,
                                              float* __restrict__ out) {
  int wid = threadIdx.x >> 5, lane = threadIdx.x & 31;
  int i = blockIdx.x * 8 + wid;
  if (i >= NN) return;
  float sdv = (lane < 8) ? g_sdst[i * 8 + lane] : 0.f;
  float arv = (lane < 8) ? arel[lane] : 0.f;
  int begin = g_rowptr[i], end = g_rowptr[i + 1];
  int deg = end - begin;
  int nIt = (deg + 31) >> 5;

  float mx = -1e30f;
  for (int j = 0; j < nIt; j++) {
    int e = begin + j * 32 + lane;
    bool act = e < end;
    int pk = g_srt[act ? e : begin];
    int src = pk & 0xFFFFF, r = pk >> 20;
    float a = g_ssrc[(size_t)src * 8 + r] + __shfl_sync(FULLMASK, sdv, r) + __shfl_sync(FULLMASK, arv, r);
    a = a > 0.f ? a : 0.2f * a;
    if (act) mx = fmaxf(mx, a);
  }
#pragma unroll
  for (int off = 16; off; off >>= 1) mx = fmaxf(mx, __shfl_xor_sync(FULLMASK, mx, off));

  float dn = 0.f;
  for (int j = 0; j < nIt; j++) {
    int e = begin + j * 32 + lane;
    bool act = e < end;
    int pk = g_srt[act ? e : begin];
    int src = pk & 0xFFFFF, r = pk >> 20;
    float a = g_ssrc[(size_t)src * 8 + r] + __shfl_sync(FULLMASK, sdv, r) + __shfl_sync(FULLMASK, arv, r);
    a = a > 0.f ? a : 0.2f * a;
    if (act) dn += __expf(a - mx);
  }
#pragma unroll
  for (int off = 16; off; off >>= 1) dn += __shfl_xor_sync(FULLMASK, dn, off);
  float iv = 1.f / dn;

  float a0 = 0.f, a1 = 0.f;
  for (int e = begin; e < end; e++) {
    int pk = g_srt[e];
    int src = pk & 0xFFFFF, r = pk >> 20;
    float a = g_ssrc[(size_t)src * 8 + r] + __shfl_sync(FULLMASK, sdv, r) + __shfl_sync(FULLMASK, arv, r);
    a = a > 0.f ? a : 0.2f * a;
    float c = __expf(a - mx) * iv;
    float2 vv = *(const float2*)(g_xw + ((size_t)src * 8 + r) * 64 + lane * 2);
    a0 = fmaf(c, vv.x, a0);
    a1 = fmaf(c, vv.y, a1);
  }
  out[(size_t)i * 64 + lane * 2]     = a0 + bias[lane * 2];
  out[(size_t)i * 64 + lane * 2 + 1] = a1 + bias[lane * 2 + 1];
}

// ---------------- launch -----------------------------------------------------
extern "C" void kernel_launch(void* const* d_in, const int* in_sizes, int n_in,
                              void* d_out, int out_size) {
  const float* x   = (const float*)d_in[0];
  const void*  ei  = d_in[1];
  const void*  et  = d_in[2];
  const float* W0  = (const float*)d_in[3];
  const float* as0 = (const float*)d_in[4];
  const float* ad0 = (const float*)d_in[5];
  const float* ar0 = (const float*)d_in[6];
  const float* bi0 = (const float*)d_in[7];
  const float* W1  = (const float*)d_in[8];
  const float* as1 = (const float*)d_in[9];
  const float* ad1 = (const float*)d_in[10];
  const float* ar1 = (const float*)d_in[11];
  const float* bi1 = (const float*)d_in[12];
  const float* W2  = (const float*)d_in[13];
  const float* as2 = (const float*)d_in[14];
  const float* ad2 = (const float*)d_in[15];
  const float* ar2 = (const float*)d_in[16];
  const float* bi2 = (const float*)d_in[17];
  const float* g0  = (const float*)d_in[18];
  const float* be0 = (const float*)d_in[19];
  const float* g1  = (const float*)d_in[20];
  const float* be1 = (const float*)d_in[21];
  float* out = (float*)d_out;

  k_detect<<<1, 64>>>((const unsigned*)ei, (const unsigned*)et);
  k_zero_deg<<<(NN + 255) / 256, 256>>>();
  k_hist<<<(NE + 255) / 256, 256>>>(ei);
  k_scan2<<<1, 1024>>>();
  k_scatter<<<(NE + 255) / 256, 256>>>(ei, et);

  const int MB = (NN + 127) / 128;  // 391

  // layer 0: in=128 -> [N,8,256]
  k_gemm_tc<<<dim3(MB, 4, 8), 256>>>(x, W0, 128, 256);
  k_srcdst4<<<(NN * NRR + 7) / 8, 256>>>(as0, ad0);
  k_agg4<<<(NN + 7) / 8, 256>>>(ar0, bi0, g0, be0);

  // layer 1: in=256 -> [N,8,256]
  k_gemm_tc<<<dim3(MB, 4, 8), 256>>>(nullptr, W1, 256, 256);
  k_srcdst4<<<(NN * NRR + 7) / 8, 256>>>(as1, ad1);
  k_agg4<<<(NN + 7) / 8, 256>>>(ar1, bi1, g1, be1);

  // layer 2: in=256 -> [N,8,64], H=1, writes output
  k_gemm_tc<<<dim3(MB, 1, 8), 256>>>(nullptr, W2, 256, 64);
  k_srcdst1<<<(NN * NRR + 7) / 8, 256>>>(as2, ad2);
  k_agg1<<<(NN + 7) / 8, 256>>>(ar2, bi2, out);
}

// round 10
// speedup vs baseline: 1.7719x; 1.5330x over previous
#include <cuda_runtime.h>
#include <cuda_bf16.h>
#include <cstdint>

#define NN 50000
#define NE 800000
#define NRR 8
#define FULLMASK 0xffffffffu

// ---------------- scratch (device globals; no allocations allowed) ----------
__device__ float g_xw[(size_t)NN * NRR * 256];     // per-(node,rel) transformed feats
__device__ float g_ssrc[NN * NRR * 4];
__device__ float g_sdst[NN * NRR * 4];
__device__ float g_h[(size_t)NN * 256];
__device__ __nv_bfloat16 g_ah[(size_t)NN * 256];   // A split hi
__device__ __nv_bfloat16 g_al[(size_t)NN * 256];   // A split lo
__device__ __nv_bfloat16 g_wh[NRR * 256 * 256];    // W split hi [r][k][d]
__device__ __nv_bfloat16 g_wl[NRR * 256 * 256];    // W split lo
__device__ int   g_deg[NN];
__device__ int   g_rowptr[NN + 1];
__device__ int   g_cursor[NN];
__device__ int   g_srt[NE];
__device__ int   g_bsum[64];
__device__ int   g_boff[64];
__device__ int   g_flags[2];

// ---------------- helpers ---------------------------------------------------
__device__ __forceinline__ int ld_i(const void* p, long long idx, int is64) {
  return is64 ? (int)((const long long*)p)[idx] : ((const int*)p)[idx];
}

__device__ __forceinline__ uint32_t smem_u32(const void* p) {
  uint32_t a;
  asm("{ .reg .u64 t; cvta.to.shared.u64 t, %1; cvt.u32.u64 %0, t; }" : "=r"(a) : "l"(p));
  return a;
}

// ---------------- mma.sync building blocks ----------------------------------
#define MMA_BF16(d, a, b)                                                     \
  asm volatile(                                                               \
      "mma.sync.aligned.m16n8k16.row.col.f32.bf16.bf16.f32 "                  \
      "{%0,%1,%2,%3},{%4,%5,%6,%7},{%8,%9},{%0,%1,%2,%3};"                    \
      : "+f"((d)[0]), "+f"((d)[1]), "+f"((d)[2]), "+f"((d)[3])                \
      : "r"((a)[0]), "r"((a)[1]), "r"((a)[2]), "r"((a)[3]),                   \
        "r"((b)[0]), "r"((b)[1]))

#define LDSM_X4(a, addr)                                                      \
  asm volatile("ldmatrix.sync.aligned.m8n8.x4.shared.b16 {%0,%1,%2,%3},[%4];" \
               : "=r"((a)[0]), "=r"((a)[1]), "=r"((a)[2]), "=r"((a)[3])       \
               : "r"(addr))

#define LDSM_X2T(b, addr)                                                     \
  asm volatile("ldmatrix.sync.aligned.m8n8.x2.trans.shared.b16 {%0,%1},[%2];" \
               : "=r"((b)[0]), "=r"((b)[1]) : "r"(addr))

#define CP16(dst, src, pred)                                                  \
  asm volatile("cp.async.cg.shared.global [%0], [%1], 16, %2;" ::"r"(dst),    \
               "l"(src), "r"((pred) ? 16 : 0))

#define CP_COMMIT() asm volatile("cp.async.commit_group;" ::: "memory")
#define CP_WAIT1() asm volatile("cp.async.wait_group 1;" ::: "memory")
#define CP_WAIT0() asm volatile("cp.async.wait_group 0;" ::: "memory")

// ---------------- graph prep -------------------------------------------------
__global__ void k_detect(const unsigned* ei, const unsigned* et) {
  int lane = threadIdx.x & 31;
  if (threadIdx.x < 32) {
    unsigned v = ei[2 * lane + 1] | ei[2 * (lane + 32) + 1];
    unsigned b = __ballot_sync(FULLMASK, v != 0u);
    if (lane == 0) g_flags[0] = (b == 0u) ? 1 : 0;
  } else {
    unsigned v = et[2 * lane + 1] | et[2 * (lane + 32) + 1];
    unsigned b = __ballot_sync(FULLMASK, v != 0u);
    if (lane == 0) g_flags[1] = (b == 0u) ? 1 : 0;
  }
}

__global__ void k_zero_deg() {
  int i = blockIdx.x * blockDim.x + threadIdx.x;
  if (i < NN) g_deg[i] = 0;
}

__global__ void k_hist(const void* ei) {
  int e = blockIdx.x * blockDim.x + threadIdx.x;
  if (e >= NE) return;
  int dst = ld_i(ei, (long long)NE + e, g_flags[0]);
  atomicAdd(&g_deg[dst], 1);
}

__global__ void k_bsum() {
  __shared__ int ws[32];
  int tid = threadIdx.x, lane = tid & 31, w = tid >> 5;
  int i = blockIdx.x * 1024 + tid;
  int v = (i < NN) ? g_deg[i] : 0;
#pragma unroll
  for (int off = 16; off; off >>= 1) v += __shfl_down_sync(FULLMASK, v, off);
  if (lane == 0) ws[w] = v;
  __syncthreads();
  if (w == 0) {
    int t = ws[lane];
#pragma unroll
    for (int off = 16; off; off >>= 1) t += __shfl_down_sync(FULLMASK, t, off);
    if (lane == 0) g_bsum[blockIdx.x] = t;
  }
}

__global__ void k_bscan(int nb) {
  __shared__ int sh[64];
  int t = threadIdx.x;
  int v = (t < nb) ? g_bsum[t] : 0;
  sh[t] = v;
  __syncthreads();
  for (int off = 1; off < 64; off <<= 1) {
    int u = (t >= off) ? sh[t - off] : 0;
    __syncthreads();
    sh[t] += u;
    __syncthreads();
  }
  if (t < nb) g_boff[t] = sh[t] - v;
  if (t == 63) g_rowptr[NN] = sh[63];
}

__global__ void k_bwrite() {
  __shared__ int ws[32];
  int tid = threadIdx.x, lane = tid & 31, w = tid >> 5;
  int i = blockIdx.x * 1024 + tid;
  int v = (i < NN) ? g_deg[i] : 0;
  int inc = v;
#pragma unroll
  for (int off = 1; off < 32; off <<= 1) {
    int t = __shfl_up_sync(FULLMASK, inc, off);
    if (lane >= off) inc += t;
  }
  if (lane == 31) ws[w] = inc;
  __syncthreads();
  if (w == 0) {
    int t = ws[lane];
#pragma unroll
    for (int off = 1; off < 32; off <<= 1) {
      int u = __shfl_up_sync(FULLMASK, t, off);
      if (lane >= off) t += u;
    }
    ws[lane] = t;
  }
  __syncthreads();
  int excl = inc - v + (w > 0 ? ws[w - 1] : 0) + g_boff[blockIdx.x];
  if (i < NN) { g_rowptr[i] = excl; g_cursor[i] = excl; }
}

__global__ void k_scatter(const void* ei, const void* et) {
  int e = blockIdx.x * blockDim.x + threadIdx.x;
  if (e >= NE) return;
  int i64e = g_flags[0], i64t = g_flags[1];
  int src = ld_i(ei, e, i64e);
  int dst = ld_i(ei, (long long)NE + e, i64e);
  int r   = ld_i(et, e, i64t);
  int pos = atomicAdd(&g_cursor[dst], 1);
  g_srt[pos] = src | (r << 20);
}

// ---------------- bf16 split precompute -------------------------------------
__device__ __forceinline__ void split1(float v, __nv_bfloat16& h, __nv_bfloat16& l) {
  h = __float2bfloat16(v);
  l = __float2bfloat16(v - __bfloat162float(h));
}

__global__ void k_split_a(const float* __restrict__ src, int K) {
  long long idx = ((long long)blockIdx.x * 256 + threadIdx.x) * 4;
  long long tot = (long long)NN * K;
  if (idx >= tot) return;
  const float* s = src ? src : g_h;
  float4 v = *(const float4*)(s + idx);
  __nv_bfloat16 h0, l0, h1, l1, h2, l2, h3, l3;
  split1(v.x, h0, l0); split1(v.y, h1, l1);
  split1(v.z, h2, l2); split1(v.w, h3, l3);
  *(__nv_bfloat162*)(g_ah + idx)     = __nv_bfloat162(h0, h1);
  *(__nv_bfloat162*)(g_ah + idx + 2) = __nv_bfloat162(h2, h3);
  *(__nv_bfloat162*)(g_al + idx)     = __nv_bfloat162(l0, l1);
  *(__nv_bfloat162*)(g_al + idx + 2) = __nv_bfloat162(l2, l3);
}

__global__ void k_split_w(const float* __restrict__ W, long long tot) {
  long long i = (long long)blockIdx.x * 256 + threadIdx.x;
  if (i >= tot) return;
  __nv_bfloat16 h, l;
  split1(W[i], h, l);
  g_wh[i] = h;
  g_wl[i] = l;
}

// ---------------- GEMM v3: mma.sync + cp.async double buffer ----------------
// xw[n, r*D+d] = sum_k A[n,k] W[r,k,d];  C = AhBh + AhBl + AlBh (fp32 acc)
// BM=128, BN=64, BK=32, 2 stages. 256 thr = 8 warps (4m x 2n), warp 32x32.
// smem strides: A row 80B (40 bf16), B row 144B (72 bf16) — cp.async-aligned,
// ldmatrix conflict-free.
#define SM_A_STAGE 10240   // 128*80
#define SM_B_STAGE 4608    // 32*144
#define SM_AL_OFF  20480
#define SM_BH_OFF  40960
#define SM_BL_OFF  50176
#define SM_TOTAL   59392

__global__ __launch_bounds__(256) void k_gemm_v3(int K, int D) {
  extern __shared__ __align__(16) char smem[];
  uint32_t sbase = smem_u32(smem);
  int tid = threadIdx.x, lane = tid & 31, wid = tid >> 5;
  int warp_m = wid >> 1, warp_n = wid & 1;
  int m0 = blockIdx.x * 128, n0 = blockIdx.y * 64, r = blockIdx.z;

  // loader indices
  int a_row = tid >> 2, a_kc = (tid & 3);          // + second chunk at tid+256
  int b_row = tid >> 3, b_dc = tid & 7;

  float acc[2][4][4];
#pragma unroll
  for (int mi = 0; mi < 2; mi++)
#pragma unroll
    for (int ni = 0; ni < 4; ni++)
#pragma unroll
      for (int q = 0; q < 4; q++) acc[mi][ni][q] = 0.f;

  int nkt = K >> 5;

  // ---- stage loader (cp.async) ----
  auto load_stage = [&](int kt) {
    int st = kt & 1;
    uint32_t sAh = sbase + st * SM_A_STAGE;
    uint32_t sAl = sbase + SM_AL_OFF + st * SM_A_STAGE;
    uint32_t sBh = sbase + SM_BH_OFF + st * SM_B_STAGE;
    uint32_t sBl = sbase + SM_BL_OFF + st * SM_B_STAGE;
    int k0 = kt * 32;
    // A: 128 rows x 32 k  (2 chunks per thread per tensor)
#pragma unroll
    for (int c = 0; c < 2; c++) {
      int row = a_row + c * 64;
      int m = m0 + row;
      bool p = m < NN;
      size_t g = (size_t)m * K + k0 + a_kc * 8;
      uint32_t so = row * 80 + a_kc * 16;
      CP16(sAh + so, g_ah + (p ? g : 0), p);
      CP16(sAl + so, g_al + (p ? g : 0), p);
    }
    // B: 32 rows(k) x 64 d (1 chunk per thread per tensor)
    {
      size_t g = ((size_t)r * K + k0 + b_row) * D + n0 + b_dc * 8;
      uint32_t so = b_row * 144 + b_dc * 16;
      CP16(sBh + so, g_wh + g, true);
      CP16(sBl + so, g_wl + g, true);
    }
    CP_COMMIT();
  };

  load_stage(0);

  for (int kt = 0; kt < nkt; kt++) {
    if (kt + 1 < nkt) load_stage(kt + 1);
    if (kt + 1 < nkt) CP_WAIT1(); else CP_WAIT0();
    __syncthreads();

    int st = kt & 1;
    uint32_t sAh = sbase + st * SM_A_STAGE;
    uint32_t sAl = sbase + SM_AL_OFF + st * SM_A_STAGE;
    uint32_t sBh = sbase + SM_BH_OFF + st * SM_B_STAGE;
    uint32_t sBl = sbase + SM_BL_OFF + st * SM_B_STAGE;

#pragma unroll
    for (int ks = 0; ks < 2; ks++) {
      uint32_t ah[2][4], al[2][4], bh[4][2], bl[4][2];
#pragma unroll
      for (int mi = 0; mi < 2; mi++) {
        uint32_t off = (uint32_t)(warp_m * 32 + mi * 16 + (lane & 15)) * 80 +
                       ks * 32 + (lane >> 4) * 16;
        LDSM_X4(ah[mi], sAh + off);
        LDSM_X4(al[mi], sAl + off);
      }
#pragma unroll
      for (int ni = 0; ni < 4; ni++) {
        uint32_t off = (uint32_t)(ks * 16 + (lane & 15)) * 144 +
                       (warp_n * 32 + ni * 8) * 2;
        LDSM_X2T(bh[ni], sBh + off);
        LDSM_X2T(bl[ni], sBl + off);
      }
#pragma unroll
      for (int mi = 0; mi < 2; mi++)
#pragma unroll
        for (int ni = 0; ni < 4; ni++) {
          MMA_BF16(acc[mi][ni], ah[mi], bh[ni]);
          MMA_BF16(acc[mi][ni], ah[mi], bl[ni]);
          MMA_BF16(acc[mi][ni], al[mi], bh[ni]);
        }
    }
    __syncthreads();
  }

  // epilogue: frag m16n8 -> rows lane>>2 (+8), cols (lane&3)*2 (+1)
  size_t rowstride = (size_t)NRR * D;
  float* outbase = g_xw + (size_t)r * D + n0;
#pragma unroll
  for (int mi = 0; mi < 2; mi++) {
    int mrow = m0 + warp_m * 32 + mi * 16 + (lane >> 2);
#pragma unroll
    for (int ni = 0; ni < 4; ni++) {
      int col = warp_n * 32 + ni * 8 + (lane & 3) * 2;
      if (mrow < NN)
        *(float2*)(outbase + (size_t)mrow * rowstride + col) =
            make_float2(acc[mi][ni][0], acc[mi][ni][1]);
      if (mrow + 8 < NN)
        *(float2*)(outbase + (size_t)(mrow + 8) * rowstride + col) =
            make_float2(acc[mi][ni][2], acc[mi][ni][3]);
    }
  }
}

// ---------------- attention scalar precompute -------------------------------
__global__ __launch_bounds__(256) void k_srcdst4(const float* __restrict__ asrc,
                                                 const float* __restrict__ adst) {
  int wid = threadIdx.x >> 5, lane = threadIdx.x & 31;
  long long p = (long long)blockIdx.x * 8 + wid;
  if (p >= (long long)NN * NRR) return;
  const float* base = g_xw + (size_t)p * 256;
  float4 x0 = *(const float4*)(base + lane * 8);
  float4 x1 = *(const float4*)(base + lane * 8 + 4);
  float4 s0 = *(const float4*)(asrc + lane * 8);
  float4 s1 = *(const float4*)(asrc + lane * 8 + 4);
  float4 d0 = *(const float4*)(adst + lane * 8);
  float4 d1 = *(const float4*)(adst + lane * 8 + 4);
  float ps = x0.x * s0.x + x0.y * s0.y + x0.z * s0.z + x0.w * s0.w +
             x1.x * s1.x + x1.y * s1.y + x1.z * s1.z + x1.w * s1.w;
  float pd = x0.x * d0.x + x0.y * d0.y + x0.z * d0.z + x0.w * d0.w +
             x1.x * d1.x + x1.y * d1.y + x1.z * d1.z + x1.w * d1.w;
#pragma unroll
  for (int off = 4; off; off >>= 1) {
    ps += __shfl_xor_sync(FULLMASK, ps, off);
    pd += __shfl_xor_sync(FULLMASK, pd, off);
  }
  if ((lane & 7) == 0) {
    g_ssrc[p * 4 + (lane >> 3)] = ps;
    g_sdst[p * 4 + (lane >> 3)] = pd;
  }
}

__global__ __launch_bounds__(256) void k_srcdst1(const float* __restrict__ asrc,
                                                 const float* __restrict__ adst) {
  int wid = threadIdx.x >> 5, lane = threadIdx.x & 31;
  long long p = (long long)blockIdx.x * 8 + wid;
  if (p >= (long long)NN * NRR) return;
  const float* base = g_xw + (size_t)p * 64;
  float2 x = *(const float2*)(base + lane * 2);
  float2 s = *(const float2*)(asrc + lane * 2);
  float2 d = *(const float2*)(adst + lane * 2);
  float ps = x.x * s.x + x.y * s.y;
  float pd = x.x * d.x + x.y * d.y;
#pragma unroll
  for (int off = 16; off; off >>= 1) {
    ps += __shfl_xor_sync(FULLMASK, ps, off);
    pd += __shfl_xor_sync(FULLMASK, pd, off);
  }
  if (lane == 0) { g_ssrc[p] = ps; g_sdst[p] = pd; }
}

// ---------------- fused attention + aggregate + bias + LN + ELU (H=4) -------
__global__ __launch_bounds__(256) void k_agg4(const float* __restrict__ arel,
                                              const float* __restrict__ bias,
                                              const float* __restrict__ gam,
                                              const float* __restrict__ bet) {
  int wid = threadIdx.x >> 5, lane = threadIdx.x & 31;
  int i = blockIdx.x * 8 + wid;
  if (i >= NN) return;
  float sdv = g_sdst[i * 32 + lane];
  float arv = arel[lane];
  int begin = g_rowptr[i], end = g_rowptr[i + 1];
  int deg = end - begin;
  int nIt = (deg + 31) >> 5;

  float mx0 = -1e30f, mx1 = -1e30f, mx2 = -1e30f, mx3 = -1e30f;
  for (int j = 0; j < nIt; j++) {
    int e = begin + j * 32 + lane;
    bool act = e < end;
    int pk = g_srt[act ? e : begin];
    int src = pk & 0xFFFFF, r = pk >> 20;
    float4 sv = *(const float4*)(g_ssrc + ((size_t)src * 8 + r) * 4);
    float a0 = sv.x + __shfl_sync(FULLMASK, sdv, r * 4 + 0) + __shfl_sync(FULLMASK, arv, r * 4 + 0);
    float a1 = sv.y + __shfl_sync(FULLMASK, sdv, r * 4 + 1) + __shfl_sync(FULLMASK, arv, r * 4 + 1);
    float a2 = sv.z + __shfl_sync(FULLMASK, sdv, r * 4 + 2) + __shfl_sync(FULLMASK, arv, r * 4 + 2);
    float a3 = sv.w + __shfl_sync(FULLMASK, sdv, r * 4 + 3) + __shfl_sync(FULLMASK, arv, r * 4 + 3);
    a0 = a0 > 0.f ? a0 : 0.2f * a0;
    a1 = a1 > 0.f ? a1 : 0.2f * a1;
    a2 = a2 > 0.f ? a2 : 0.2f * a2;
    a3 = a3 > 0.f ? a3 : 0.2f * a3;
    if (act) {
      mx0 = fmaxf(mx0, a0); mx1 = fmaxf(mx1, a1);
      mx2 = fmaxf(mx2, a2); mx3 = fmaxf(mx3, a3);
    }
  }
#pragma unroll
  for (int off = 16; off; off >>= 1) {
    mx0 = fmaxf(mx0, __shfl_xor_sync(FULLMASK, mx0, off));
    mx1 = fmaxf(mx1, __shfl_xor_sync(FULLMASK, mx1, off));
    mx2 = fmaxf(mx2, __shfl_xor_sync(FULLMASK, mx2, off));
    mx3 = fmaxf(mx3, __shfl_xor_sync(FULLMASK, mx3, off));
  }

  float dn0 = 0.f, dn1 = 0.f, dn2 = 0.f, dn3 = 0.f;
  for (int j = 0; j < nIt; j++) {
    int e = begin + j * 32 + lane;
    bool act = e < end;
    int pk = g_srt[act ? e : begin];
    int src = pk & 0xFFFFF, r = pk >> 20;
    float4 sv = *(const float4*)(g_ssrc + ((size_t)src * 8 + r) * 4);
    float a0 = sv.x + __shfl_sync(FULLMASK, sdv, r * 4 + 0) + __shfl_sync(FULLMASK, arv, r * 4 + 0);
    float a1 = sv.y + __shfl_sync(FULLMASK, sdv, r * 4 + 1) + __shfl_sync(FULLMASK, arv, r * 4 + 1);
    float a2 = sv.z + __shfl_sync(FULLMASK, sdv, r * 4 + 2) + __shfl_sync(FULLMASK, arv, r * 4 + 2);
    float a3 = sv.w + __shfl_sync(FULLMASK, sdv, r * 4 + 3) + __shfl_sync(FULLMASK, arv, r * 4 + 3);
    a0 = a0 > 0.f ? a0 : 0.2f * a0;
    a1 = a1 > 0.f ? a1 : 0.2f * a1;
    a2 = a2 > 0.f ? a2 : 0.2f * a2;
    a3 = a3 > 0.f ? a3 : 0.2f * a3;
    if (act) {
      dn0 += __expf(a0 - mx0); dn1 += __expf(a1 - mx1);
      dn2 += __expf(a2 - mx2); dn3 += __expf(a3 - mx3);
    }
  }
#pragma unroll
  for (int off = 16; off; off >>= 1) {
    dn0 += __shfl_xor_sync(FULLMASK, dn0, off);
    dn1 += __shfl_xor_sync(FULLMASK, dn1, off);
    dn2 += __shfl_xor_sync(FULLMASK, dn2, off);
    dn3 += __shfl_xor_sync(FULLMASK, dn3, off);
  }
  float iv0 = 1.f / dn0, iv1 = 1.f / dn1, iv2 = 1.f / dn2, iv3 = 1.f / dn3;

  float acc0 = 0.f, acc1 = 0.f, acc2 = 0.f, acc3 = 0.f;
  float acc4 = 0.f, acc5 = 0.f, acc6 = 0.f, acc7 = 0.f;
  int h = lane >> 3;
  for (int e = begin; e < end; e++) {
    int pk = g_srt[e];
    int src = pk & 0xFFFFF, r = pk >> 20;
    float4 sv = *(const float4*)(g_ssrc + ((size_t)src * 8 + r) * 4);
    float a0 = sv.x + __shfl_sync(FULLMASK, sdv, r * 4 + 0) + __shfl_sync(FULLMASK, arv, r * 4 + 0);
    float a1 = sv.y + __shfl_sync(FULLMASK, sdv, r * 4 + 1) + __shfl_sync(FULLMASK, arv, r * 4 + 1);
    float a2 = sv.z + __shfl_sync(FULLMASK, sdv, r * 4 + 2) + __shfl_sync(FULLMASK, arv, r * 4 + 2);
    float a3 = sv.w + __shfl_sync(FULLMASK, sdv, r * 4 + 3) + __shfl_sync(FULLMASK, arv, r * 4 + 3);
    a0 = a0 > 0.f ? a0 : 0.2f * a0;
    a1 = a1 > 0.f ? a1 : 0.2f * a1;
    a2 = a2 > 0.f ? a2 : 0.2f * a2;
    a3 = a3 > 0.f ? a3 : 0.2f * a3;
    float c0 = __expf(a0 - mx0) * iv0;
    float c1 = __expf(a1 - mx1) * iv1;
    float c2 = __expf(a2 - mx2) * iv2;
    float c3 = __expf(a3 - mx3) * iv3;
    float c = (h == 0) ? c0 : (h == 1) ? c1 : (h == 2) ? c2 : c3;
    const float* xp = g_xw + ((size_t)src * 8 + r) * 256 + lane * 8;
    float4 v0 = *(const float4*)xp;
    float4 v1 = *(const float4*)(xp + 4);
    acc0 = fmaf(c, v0.x, acc0); acc1 = fmaf(c, v0.y, acc1);
    acc2 = fmaf(c, v0.z, acc2); acc3 = fmaf(c, v0.w, acc3);
    acc4 = fmaf(c, v1.x, acc4); acc5 = fmaf(c, v1.y, acc5);
    acc6 = fmaf(c, v1.z, acc6); acc7 = fmaf(c, v1.w, acc7);
  }

  float4 b0 = *(const float4*)(bias + lane * 8);
  float4 b1 = *(const float4*)(bias + lane * 8 + 4);
  float w0 = acc0 + b0.x, w1 = acc1 + b0.y, w2 = acc2 + b0.z, w3 = acc3 + b0.w;
  float w4 = acc4 + b1.x, w5 = acc5 + b1.y, w6 = acc6 + b1.z, w7 = acc7 + b1.w;
  float s  = w0 + w1 + w2 + w3 + w4 + w5 + w6 + w7;
  float ss = w0 * w0 + w1 * w1 + w2 * w2 + w3 * w3 + w4 * w4 + w5 * w5 + w6 * w6 + w7 * w7;
#pragma unroll
  for (int off = 16; off; off >>= 1) {
    s  += __shfl_xor_sync(FULLMASK, s, off);
    ss += __shfl_xor_sync(FULLMASK, ss, off);
  }
  float mean = s * (1.f / 256.f);
  float var  = fmaxf(ss * (1.f / 256.f) - mean * mean, 0.f);
  float inv  = rsqrtf(var + 1e-5f);
  float4 gg0 = *(const float4*)(gam + lane * 8);
  float4 gg1 = *(const float4*)(gam + lane * 8 + 4);
  float4 bb0 = *(const float4*)(bet + lane * 8);
  float4 bb1 = *(const float4*)(bet + lane * 8 + 4);
  float o0 = (w0 - mean) * inv * gg0.x + bb0.x;
  float o1 = (w1 - mean) * inv * gg0.y + bb0.y;
  float o2 = (w2 - mean) * inv * gg0.z + bb0.z;
  float o3 = (w3 - mean) * inv * gg0.w + bb0.w;
  float o4 = (w4 - mean) * inv * gg1.x + bb1.x;
  float o5 = (w5 - mean) * inv * gg1.y + bb1.y;
  float o6 = (w6 - mean) * inv * gg1.z + bb1.z;
  float o7 = (w7 - mean) * inv * gg1.w + bb1.w;
  o0 = o0 > 0.f ? o0 : expm1f(o0);
  o1 = o1 > 0.f ? o1 : expm1f(o1);
  o2 = o2 > 0.f ? o2 : expm1f(o2);
  o3 = o3 > 0.f ? o3 : expm1f(o3);
  o4 = o4 > 0.f ? o4 : expm1f(o4);
  o5 = o5 > 0.f ? o5 : expm1f(o5);
  o6 = o6 > 0.f ? o6 : expm1f(o6);
  o7 = o7 > 0.f ? o7 : expm1f(o7);
  float* op = g_h + (size_t)i * 256 + lane * 8;
  *(float4*)op       = make_float4(o0, o1, o2, o3);
  *(float4*)(op + 4) = make_float4(o4, o5, o6, o7);
}

// ---------------- final layer: H=1, D=64, writes d_out ----------------------
__global__ __launch_bounds__(256) void k_agg1(const float* __restrict__ arel,
                                              const float* __restrict__ bias,
                                              float* __restrict__ out) {
  int wid = threadIdx.x >> 5, lane = threadIdx.x & 31;
  int i = blockIdx.x * 8 + wid;
  if (i >= NN) return;
  float sdv = (lane < 8) ? g_sdst[i * 8 + lane] : 0.f;
  float arv = (lane < 8) ? arel[lane] : 0.f;
  int begin = g_rowptr[i], end = g_rowptr[i + 1];
  int deg = end - begin;
  int nIt = (deg + 31) >> 5;

  float mx = -1e30f;
  for (int j = 0; j < nIt; j++) {
    int e = begin + j * 32 + lane;
    bool act = e < end;
    int pk = g_srt[act ? e : begin];
    int src = pk & 0xFFFFF, r = pk >> 20;
    float a = g_ssrc[(size_t)src * 8 + r] + __shfl_sync(FULLMASK, sdv, r) + __shfl_sync(FULLMASK, arv, r);
    a = a > 0.f ? a : 0.2f * a;
    if (act) mx = fmaxf(mx, a);
  }
#pragma unroll
  for (int off = 16; off; off >>= 1) mx = fmaxf(mx, __shfl_xor_sync(FULLMASK, mx, off));

  float dn = 0.f;
  for (int j = 0; j < nIt; j++) {
    int e = begin + j * 32 + lane;
    bool act = e < end;
    int pk = g_srt[act ? e : begin];
    int src = pk & 0xFFFFF, r = pk >> 20;
    float a = g_ssrc[(size_t)src * 8 + r] + __shfl_sync(FULLMASK, sdv, r) + __shfl_sync(FULLMASK, arv, r);
    a = a > 0.f ? a : 0.2f * a;
    if (act) dn += __expf(a - mx);
  }
#pragma unroll
  for (int off = 16; off; off >>= 1) dn += __shfl_xor_sync(FULLMASK, dn, off);
  float iv = 1.f / dn;

  float a0 = 0.f, a1 = 0.f;
  for (int e = begin; e < end; e++) {
    int pk = g_srt[e];
    int src = pk & 0xFFFFF, r = pk >> 20;
    float a = g_ssrc[(size_t)src * 8 + r] + __shfl_sync(FULLMASK, sdv, r) + __shfl_sync(FULLMASK, arv, r);
    a = a > 0.f ? a : 0.2f * a;
    float c = __expf(a - mx) * iv;
    float2 vv = *(const float2*)(g_xw + ((size_t)src * 8 + r) * 64 + lane * 2);
    a0 = fmaf(c, vv.x, a0);
    a1 = fmaf(c, vv.y, a1);
  }
  out[(size_t)i * 64 + lane * 2]     = a0 + bias[lane * 2];
  out[(size_t)i * 64 + lane * 2 + 1] = a1 + bias[lane * 2 + 1];
}

// ---------------- launch -----------------------------------------------------
extern "C" void kernel_launch(void* const* d_in, const int* in_sizes, int n_in,
                              void* d_out, int out_size) {
  const float* x   = (const float*)d_in[0];
  const void*  ei  = d_in[1];
  const void*  et  = d_in[2];
  const float* W0  = (const float*)d_in[3];
  const float* as0 = (const float*)d_in[4];
  const float* ad0 = (const float*)d_in[5];
  const float* ar0 = (const float*)d_in[6];
  const float* bi0 = (const float*)d_in[7];
  const float* W1  = (const float*)d_in[8];
  const float* as1 = (const float*)d_in[9];
  const float* ad1 = (const float*)d_in[10];
  const float* ar1 = (const float*)d_in[11];
  const float* bi1 = (const float*)d_in[12];
  const float* W2  = (const float*)d_in[13];
  const float* as2 = (const float*)d_in[14];
  const float* ad2 = (const float*)d_in[15];
  const float* ar2 = (const float*)d_in[16];
  const float* bi2 = (const float*)d_in[17];
  const float* g0  = (const float*)d_in[18];
  const float* be0 = (const float*)d_in[19];
  const float* g1  = (const float*)d_in[20];
  const float* be1 = (const float*)d_in[21];
  float* out = (float*)d_out;

  cudaFuncSetAttribute(k_gemm_v3, cudaFuncAttributeMaxDynamicSharedMemorySize, SM_TOTAL);

  // graph prep
  k_detect<<<1, 64>>>((const unsigned*)ei, (const unsigned*)et);
  k_zero_deg<<<(NN + 255) / 256, 256>>>();
  k_hist<<<(NE + 255) / 256, 256>>>(ei);
  const int NB = (NN + 1023) / 1024;  // 49
  k_bsum<<<NB, 1024>>>();
  k_bscan<<<1, 64>>>(NB);
  k_bwrite<<<NB, 1024>>>();
  k_scatter<<<(NE + 255) / 256, 256>>>(ei, et);

  const int MB = (NN + 127) / 128;  // 391

  // layer 0: K=128, D=256
  k_split_a<<<(int)(((long long)NN * 128 / 4 + 255) / 256), 256>>>(x, 128);
  k_split_w<<<(int)((8LL * 128 * 256 + 255) / 256), 256>>>(W0, 8LL * 128 * 256);
  k_gemm_v3<<<dim3(MB, 4, 8), 256, SM_TOTAL>>>(128, 256);
  k_srcdst4<<<(NN * NRR + 7) / 8, 256>>>(as0, ad0);
  k_agg4<<<(NN + 7) / 8, 256>>>(ar0, bi0, g0, be0);

  // layer 1: K=256, D=256
  k_split_a<<<(int)(((long long)NN * 256 / 4 + 255) / 256), 256>>>(nullptr, 256);
  k_split_w<<<(int)((8LL * 256 * 256 + 255) / 256), 256>>>(W1, 8LL * 256 * 256);
  k_gemm_v3<<<dim3(MB, 4, 8), 256, SM_TOTAL>>>(256, 256);
  k_srcdst4<<<(NN * NRR + 7) / 8, 256>>>(as1, ad1);
  k_agg4<<<(NN + 7) / 8, 256>>>(ar1, bi1, g1, be1);

  // layer 2: K=256, D=64 (re-split A: g_h changed after layer-1 agg)
  k_split_a<<<(int)(((long long)NN * 256 / 4 + 255) / 256), 256>>>(nullptr, 256);
  k_split_w<<<(int)((8LL * 256 * 64 + 255) / 256), 256>>>(W2, 8LL * 256 * 64);
  k_gemm_v3<<<dim3(MB, 1, 8), 256, SM_TOTAL>>>(256, 64);
  k_srcdst1<<<(NN * NRR + 7) / 8, 256>>>(as2, ad2);
  k_agg1<<<(NN + 7) / 8, 256>>>(ar2, bi2, out);
}

// round 12
// speedup vs baseline: 1.9223x; 1.0849x over previous
#include <cuda_runtime.h>
#include <cuda_bf16.h>
#include <cstdint>

#define NN 50000
#define NE 800000
#define NRR 8
#define FULLMASK 0xffffffffu

// ---------------- scratch (device globals; no allocations allowed) ----------
__device__ float g_xw[(size_t)NN * NRR * 256];     // per-(node,rel) transformed feats
__device__ float g_ssrc[NN * NRR * 4];
__device__ float g_sdst[NN * NRR * 4];
__device__ __nv_bfloat16 g_ah[(size_t)NN * 256];   // A split hi
__device__ __nv_bfloat16 g_al[(size_t)NN * 256];   // A split lo
__device__ __nv_bfloat16 g_wh[NRR * 256 * 256];    // W split hi [r][k][d]
__device__ __nv_bfloat16 g_wl[NRR * 256 * 256];    // W split lo
__device__ int   g_deg[NN];
__device__ int   g_rowptr[NN + 1];
__device__ int   g_cursor[NN];
__device__ int   g_srt[NE];
__device__ int   g_bsum[64];
__device__ int   g_boff[64];
__device__ int   g_flags[2];

// ---------------- helpers ---------------------------------------------------
__device__ __forceinline__ int ld_i(const void* p, long long idx, int is64) {
  return is64 ? (int)((const long long*)p)[idx] : ((const int*)p)[idx];
}

__device__ __forceinline__ uint32_t smem_u32(const void* p) {
  uint32_t a;
  asm("{ .reg .u64 t; cvta.to.shared.u64 t, %1; cvt.u32.u64 %0, t; }" : "=r"(a) : "l"(p));
  return a;
}

// ---------------- mma.sync building blocks ----------------------------------
#define MMA_BF16(d, a, b)                                                     \
  asm volatile(                                                               \
      "mma.sync.aligned.m16n8k16.row.col.f32.bf16.bf16.f32 "                  \
      "{%0,%1,%2,%3},{%4,%5,%6,%7},{%8,%9},{%0,%1,%2,%3};"                    \
      : "+f"((d)[0]), "+f"((d)[1]), "+f"((d)[2]), "+f"((d)[3])                \
      : "r"((a)[0]), "r"((a)[1]), "r"((a)[2]), "r"((a)[3]),                   \
        "r"((b)[0]), "r"((b)[1]))

#define LDSM_X4(a, addr)                                                      \
  asm volatile("ldmatrix.sync.aligned.m8n8.x4.shared.b16 {%0,%1,%2,%3},[%4];" \
               : "=r"((a)[0]), "=r"((a)[1]), "=r"((a)[2]), "=r"((a)[3])       \
               : "r"(addr))

#define LDSM_X2T(b, addr)                                                     \
  asm volatile("ldmatrix.sync.aligned.m8n8.x2.trans.shared.b16 {%0,%1},[%2];" \
               : "=r"((b)[0]), "=r"((b)[1]) : "r"(addr))

#define CP16(dst, src, pred)                                                  \
  asm volatile("cp.async.cg.shared.global [%0], [%1], 16, %2;" ::"r"(dst),    \
               "l"(src), "r"((pred) ? 16 : 0))

#define CP_COMMIT() asm volatile("cp.async.commit_group;" ::: "memory")
#define CP_WAIT1() asm volatile("cp.async.wait_group 1;" ::: "memory")
#define CP_WAIT0() asm volatile("cp.async.wait_group 0;" ::: "memory")

// ---------------- graph prep -------------------------------------------------
__global__ void k_detect(const unsigned* ei, const unsigned* et) {
  int lane = threadIdx.x & 31;
  if (threadIdx.x < 32) {
    unsigned v = ei[2 * lane + 1] | ei[2 * (lane + 32) + 1];
    unsigned b = __ballot_sync(FULLMASK, v != 0u);
    if (lane == 0) g_flags[0] = (b == 0u) ? 1 : 0;
  } else {
    unsigned v = et[2 * lane + 1] | et[2 * (lane + 32) + 1];
    unsigned b = __ballot_sync(FULLMASK, v != 0u);
    if (lane == 0) g_flags[1] = (b == 0u) ? 1 : 0;
  }
}

__global__ void k_zero_deg() {
  int i = blockIdx.x * blockDim.x + threadIdx.x;
  if (i < NN) g_deg[i] = 0;
}

__global__ void k_zero_s(int n) {
  int i = blockIdx.x * 256 + threadIdx.x;
  if (i < n) { g_ssrc[i] = 0.f; g_sdst[i] = 0.f; }
}

__global__ void k_hist(const void* ei) {
  int e = blockIdx.x * blockDim.x + threadIdx.x;
  if (e >= NE) return;
  int dst = ld_i(ei, (long long)NE + e, g_flags[0]);
  atomicAdd(&g_deg[dst], 1);
}

__global__ void k_bsum() {
  __shared__ int ws[32];
  int tid = threadIdx.x, lane = tid & 31, w = tid >> 5;
  int i = blockIdx.x * 1024 + tid;
  int v = (i < NN) ? g_deg[i] : 0;
#pragma unroll
  for (int off = 16; off; off >>= 1) v += __shfl_down_sync(FULLMASK, v, off);
  if (lane == 0) ws[w] = v;
  __syncthreads();
  if (w == 0) {
    int t = ws[lane];
#pragma unroll
    for (int off = 16; off; off >>= 1) t += __shfl_down_sync(FULLMASK, t, off);
    if (lane == 0) g_bsum[blockIdx.x] = t;
  }
}

__global__ void k_bscan(int nb) {
  __shared__ int sh[64];
  int t = threadIdx.x;
  int v = (t < nb) ? g_bsum[t] : 0;
  sh[t] = v;
  __syncthreads();
  for (int off = 1; off < 64; off <<= 1) {
    int u = (t >= off) ? sh[t - off] : 0;
    __syncthreads();
    sh[t] += u;
    __syncthreads();
  }
  if (t < nb) g_boff[t] = sh[t] - v;
  if (t == 63) g_rowptr[NN] = sh[63];
}

__global__ void k_bwrite() {
  __shared__ int ws[32];
  int tid = threadIdx.x, lane = tid & 31, w = tid >> 5;
  int i = blockIdx.x * 1024 + tid;
  int v = (i < NN) ? g_deg[i] : 0;
  int inc = v;
#pragma unroll
  for (int off = 1; off < 32; off <<= 1) {
    int t = __shfl_up_sync(FULLMASK, inc, off);
    if (lane >= off) inc += t;
  }
  if (lane == 31) ws[w] = inc;
  __syncthreads();
  if (w == 0) {
    int t = ws[lane];
#pragma unroll
    for (int off = 1; off < 32; off <<= 1) {
      int u = __shfl_up_sync(FULLMASK, t, off);
      if (lane >= off) t += u;
    }
    ws[lane] = t;
  }
  __syncthreads();
  int excl = inc - v + (w > 0 ? ws[w - 1] : 0) + g_boff[blockIdx.x];
  if (i < NN) { g_rowptr[i] = excl; g_cursor[i] = excl; }
}

__global__ void k_scatter(const void* ei, const void* et) {
  int e = blockIdx.x * blockDim.x + threadIdx.x;
  if (e >= NE) return;
  int i64e = g_flags[0], i64t = g_flags[1];
  int src = ld_i(ei, e, i64e);
  int dst = ld_i(ei, (long long)NE + e, i64e);
  int r   = ld_i(et, e, i64t);
  int pos = atomicAdd(&g_cursor[dst], 1);
  g_srt[pos] = src | (r << 20);
}

// ---------------- bf16 split precompute -------------------------------------
__device__ __forceinline__ void split1(float v, __nv_bfloat16& h, __nv_bfloat16& l) {
  h = __float2bfloat16(v);
  l = __float2bfloat16(v - __bfloat162float(h));
}

__global__ void k_split_a(const float* __restrict__ src, int K) {
  long long idx = ((long long)blockIdx.x * 256 + threadIdx.x) * 4;
  long long tot = (long long)NN * K;
  if (idx >= tot) return;
  float4 v = *(const float4*)(src + idx);
  __nv_bfloat16 h0, l0, h1, l1, h2, l2, h3, l3;
  split1(v.x, h0, l0); split1(v.y, h1, l1);
  split1(v.z, h2, l2); split1(v.w, h3, l3);
  *(__nv_bfloat162*)(g_ah + idx)     = __nv_bfloat162(h0, h1);
  *(__nv_bfloat162*)(g_ah + idx + 2) = __nv_bfloat162(h2, h3);
  *(__nv_bfloat162*)(g_al + idx)     = __nv_bfloat162(l0, l1);
  *(__nv_bfloat162*)(g_al + idx + 2) = __nv_bfloat162(l2, l3);
}

__global__ void k_split_w(const float* __restrict__ W, long long tot) {
  long long i = (long long)blockIdx.x * 256 + threadIdx.x;
  if (i >= tot) return;
  __nv_bfloat16 h, l;
  split1(W[i], h, l);
  g_wh[i] = h;
  g_wl[i] = l;
}

// ---------------- GEMM v4: mma.sync + cp.async + fused srcdst epilogue ------
// xw[n, r*D+d] = sum_k A[n,k] W[r,k,d];  C = AhBh + AhBl + AlBh (fp32 acc)
// BM=128, BN=64, BK=32, 2 stages. BN == head width C=64, so this block's
// columns are exactly head h = blockIdx.y: ssrc/sdst computed in epilogue.
#define SM_A_STAGE 10240   // 128*80
#define SM_B_STAGE 4608    // 32*144
#define SM_AL_OFF  20480
#define SM_BH_OFF  40960
#define SM_BL_OFF  50176
#define SM_TOTAL   59392

__global__ __launch_bounds__(256) void k_gemm_v4(int K, int D,
                                                 const float* __restrict__ asrc,
                                                 const float* __restrict__ adst,
                                                 int H) {
  extern __shared__ __align__(16) char smem[];
  uint32_t sbase = smem_u32(smem);
  int tid = threadIdx.x, lane = tid & 31, wid = tid >> 5;
  int warp_m = wid >> 1, warp_n = wid & 1;
  int m0 = blockIdx.x * 128, n0 = blockIdx.y * 64, r = blockIdx.z;
  int h = blockIdx.y;

  int a_row = tid >> 2, a_kc = (tid & 3);
  int b_row = tid >> 3, b_dc = tid & 7;

  float acc[2][4][4];
#pragma unroll
  for (int mi = 0; mi < 2; mi++)
#pragma unroll
    for (int ni = 0; ni < 4; ni++)
#pragma unroll
      for (int q = 0; q < 4; q++) acc[mi][ni][q] = 0.f;

  int nkt = K >> 5;

  auto load_stage = [&](int kt) {
    int st = kt & 1;
    uint32_t sAh = sbase + st * SM_A_STAGE;
    uint32_t sAl = sbase + SM_AL_OFF + st * SM_A_STAGE;
    uint32_t sBh = sbase + SM_BH_OFF + st * SM_B_STAGE;
    uint32_t sBl = sbase + SM_BL_OFF + st * SM_B_STAGE;
    int k0 = kt * 32;
#pragma unroll
    for (int c = 0; c < 2; c++) {
      int row = a_row + c * 64;
      int m = m0 + row;
      bool p = m < NN;
      size_t g = (size_t)m * K + k0 + a_kc * 8;
      uint32_t so = row * 80 + a_kc * 16;
      CP16(sAh + so, g_ah + (p ? g : 0), p);
      CP16(sAl + so, g_al + (p ? g : 0), p);
    }
    {
      size_t g = ((size_t)r * K + k0 + b_row) * D + n0 + b_dc * 8;
      uint32_t so = b_row * 144 + b_dc * 16;
      CP16(sBh + so, g_wh + g, true);
      CP16(sBl + so, g_wl + g, true);
    }
    CP_COMMIT();
  };

  load_stage(0);

  for (int kt = 0; kt < nkt; kt++) {
    if (kt + 1 < nkt) load_stage(kt + 1);
    if (kt + 1 < nkt) CP_WAIT1(); else CP_WAIT0();
    __syncthreads();

    int st = kt & 1;
    uint32_t sAh = sbase + st * SM_A_STAGE;
    uint32_t sAl = sbase + SM_AL_OFF + st * SM_A_STAGE;
    uint32_t sBh = sbase + SM_BH_OFF + st * SM_B_STAGE;
    uint32_t sBl = sbase + SM_BL_OFF + st * SM_B_STAGE;

#pragma unroll
    for (int ks = 0; ks < 2; ks++) {
      uint32_t ah[2][4], al[2][4], bh[4][2], bl[4][2];
#pragma unroll
      for (int mi = 0; mi < 2; mi++) {
        uint32_t off = (uint32_t)(warp_m * 32 + mi * 16 + (lane & 15)) * 80 +
                       ks * 32 + (lane >> 4) * 16;
        LDSM_X4(ah[mi], sAh + off);
        LDSM_X4(al[mi], sAl + off);
      }
#pragma unroll
      for (int ni = 0; ni < 4; ni++) {
        uint32_t off = (uint32_t)(ks * 16 + (lane & 15)) * 144 +
                       (warp_n * 32 + ni * 8) * 2;
        LDSM_X2T(bh[ni], sBh + off);
        LDSM_X2T(bl[ni], sBl + off);
      }
#pragma unroll
      for (int mi = 0; mi < 2; mi++)
#pragma unroll
        for (int ni = 0; ni < 4; ni++) {
          MMA_BF16(acc[mi][ni], ah[mi], bh[ni]);
          MMA_BF16(acc[mi][ni], ah[mi], bl[ni]);
          MMA_BF16(acc[mi][ni], al[mi], bh[ni]);
        }
    }
    __syncthreads();
  }

  // ---- epilogue 1: store xw ----
  size_t rowstride = (size_t)NRR * D;
  float* outbase = g_xw + (size_t)r * D + n0;
#pragma unroll
  for (int mi = 0; mi < 2; mi++) {
    int mrow = m0 + warp_m * 32 + mi * 16 + (lane >> 2);
#pragma unroll
    for (int ni = 0; ni < 4; ni++) {
      int col = warp_n * 32 + ni * 8 + (lane & 3) * 2;
      if (mrow < NN)
        *(float2*)(outbase + (size_t)mrow * rowstride + col) =
            make_float2(acc[mi][ni][0], acc[mi][ni][1]);
      if (mrow + 8 < NN)
        *(float2*)(outbase + (size_t)(mrow + 8) * rowstride + col) =
            make_float2(acc[mi][ni][2], acc[mi][ni][3]);
    }
  }

  // ---- epilogue 2: fused ssrc/sdst (this block == one full head slice) ----
  float2 sa[4], da[4];
#pragma unroll
  for (int ni = 0; ni < 4; ni++) {
    int col = h * 64 + warp_n * 32 + ni * 8 + (lane & 3) * 2;
    sa[ni] = *(const float2*)(asrc + col);
    da[ni] = *(const float2*)(adst + col);
  }
#pragma unroll
  for (int mi = 0; mi < 2; mi++) {
    float p0s = 0.f, p1s = 0.f, p0d = 0.f, p1d = 0.f;
#pragma unroll
    for (int ni = 0; ni < 4; ni++) {
      p0s += acc[mi][ni][0] * sa[ni].x + acc[mi][ni][1] * sa[ni].y;
      p1s += acc[mi][ni][2] * sa[ni].x + acc[mi][ni][3] * sa[ni].y;
      p0d += acc[mi][ni][0] * da[ni].x + acc[mi][ni][1] * da[ni].y;
      p1d += acc[mi][ni][2] * da[ni].x + acc[mi][ni][3] * da[ni].y;
    }
    // reduce across the 4 quad lanes (same row, different col groups)
#pragma unroll
    for (int off = 1; off <= 2; off <<= 1) {
      p0s += __shfl_xor_sync(FULLMASK, p0s, off);
      p1s += __shfl_xor_sync(FULLMASK, p1s, off);
      p0d += __shfl_xor_sync(FULLMASK, p0d, off);
      p1d += __shfl_xor_sync(FULLMASK, p1d, off);
    }
    if ((lane & 3) == 0) {
      int m = m0 + warp_m * 32 + mi * 16 + (lane >> 2);
      if (m < NN) {
        atomicAdd(&g_ssrc[((size_t)m * NRR + r) * H + h], p0s);
        atomicAdd(&g_sdst[((size_t)m * NRR + r) * H + h], p0d);
      }
      if (m + 8 < NN) {
        atomicAdd(&g_ssrc[((size_t)(m + 8) * NRR + r) * H + h], p1s);
        atomicAdd(&g_sdst[((size_t)(m + 8) * NRR + r) * H + h], p1d);
      }
    }
  }
}

// ---------------- fused attention + aggregate + bias + LN + ELU (H=4) -------
// epilogue also writes bf16 hi/lo split of the output (next layer's A).
__global__ __launch_bounds__(256) void k_agg4(const float* __restrict__ arel,
                                              const float* __restrict__ bias,
                                              const float* __restrict__ gam,
                                              const float* __restrict__ bet) {
  int wid = threadIdx.x >> 5, lane = threadIdx.x & 31;
  int i = blockIdx.x * 8 + wid;
  if (i >= NN) return;
  float sdv = g_sdst[i * 32 + lane];
  float arv = arel[lane];
  int begin = g_rowptr[i], end = g_rowptr[i + 1];
  int deg = end - begin;
  int nIt = (deg + 31) >> 5;

  float mx0 = -1e30f, mx1 = -1e30f, mx2 = -1e30f, mx3 = -1e30f;
  for (int j = 0; j < nIt; j++) {
    int e = begin + j * 32 + lane;
    bool act = e < end;
    int pk = g_srt[act ? e : begin];
    int src = pk & 0xFFFFF, r = pk >> 20;
    float4 sv = *(const float4*)(g_ssrc + ((size_t)src * 8 + r) * 4);
    float a0 = sv.x + __shfl_sync(FULLMASK, sdv, r * 4 + 0) + __shfl_sync(FULLMASK, arv, r * 4 + 0);
    float a1 = sv.y + __shfl_sync(FULLMASK, sdv, r * 4 + 1) + __shfl_sync(FULLMASK, arv, r * 4 + 1);
    float a2 = sv.z + __shfl_sync(FULLMASK, sdv, r * 4 + 2) + __shfl_sync(FULLMASK, arv, r * 4 + 2);
    float a3 = sv.w + __shfl_sync(FULLMASK, sdv, r * 4 + 3) + __shfl_sync(FULLMASK, arv, r * 4 + 3);
    a0 = a0 > 0.f ? a0 : 0.2f * a0;
    a1 = a1 > 0.f ? a1 : 0.2f * a1;
    a2 = a2 > 0.f ? a2 : 0.2f * a2;
    a3 = a3 > 0.f ? a3 : 0.2f * a3;
    if (act) {
      mx0 = fmaxf(mx0, a0); mx1 = fmaxf(mx1, a1);
      mx2 = fmaxf(mx2, a2); mx3 = fmaxf(mx3, a3);
    }
  }
#pragma unroll
  for (int off = 16; off; off >>= 1) {
    mx0 = fmaxf(mx0, __shfl_xor_sync(FULLMASK, mx0, off));
    mx1 = fmaxf(mx1, __shfl_xor_sync(FULLMASK, mx1, off));
    mx2 = fmaxf(mx2, __shfl_xor_sync(FULLMASK, mx2, off));
    mx3 = fmaxf(mx3, __shfl_xor_sync(FULLMASK, mx3, off));
  }

  float dn0 = 0.f, dn1 = 0.f, dn2 = 0.f, dn3 = 0.f;
  for (int j = 0; j < nIt; j++) {
    int e = begin + j * 32 + lane;
    bool act = e < end;
    int pk = g_srt[act ? e : begin];
    int src = pk & 0xFFFFF, r = pk >> 20;
    float4 sv = *(const float4*)(g_ssrc + ((size_t)src * 8 + r) * 4);
    float a0 = sv.x + __shfl_sync(FULLMASK, sdv, r * 4 + 0) + __shfl_sync(FULLMASK, arv, r * 4 + 0);
    float a1 = sv.y + __shfl_sync(FULLMASK, sdv, r * 4 + 1) + __shfl_sync(FULLMASK, arv, r * 4 + 1);
    float a2 = sv.z + __shfl_sync(FULLMASK, sdv, r * 4 + 2) + __shfl_sync(FULLMASK, arv, r * 4 + 2);
    float a3 = sv.w + __shfl_sync(FULLMASK, sdv, r * 4 + 3) + __shfl_sync(FULLMASK, arv, r * 4 + 3);
    a0 = a0 > 0.f ? a0 : 0.2f * a0;
    a1 = a1 > 0.f ? a1 : 0.2f * a1;
    a2 = a2 > 0.f ? a2 : 0.2f * a2;
    a3 = a3 > 0.f ? a3 : 0.2f * a3;
    if (act) {
      dn0 += __expf(a0 - mx0); dn1 += __expf(a1 - mx1);
      dn2 += __expf(a2 - mx2); dn3 += __expf(a3 - mx3);
    }
  }
#pragma unroll
  for (int off = 16; off; off >>= 1) {
    dn0 += __shfl_xor_sync(FULLMASK, dn0, off);
    dn1 += __shfl_xor_sync(FULLMASK, dn1, off);
    dn2 += __shfl_xor_sync(FULLMASK, dn2, off);
    dn3 += __shfl_xor_sync(FULLMASK, dn3, off);
  }
  float iv0 = 1.f / dn0, iv1 = 1.f / dn1, iv2 = 1.f / dn2, iv3 = 1.f / dn3;

  float acc0 = 0.f, acc1 = 0.f, acc2 = 0.f, acc3 = 0.f;
  float acc4 = 0.f, acc5 = 0.f, acc6 = 0.f, acc7 = 0.f;
  int h = lane >> 3;
  for (int e = begin; e < end; e++) {
    int pk = g_srt[e];
    int src = pk & 0xFFFFF, r = pk >> 20;
    float4 sv = *(const float4*)(g_ssrc + ((size_t)src * 8 + r) * 4);
    float a0 = sv.x + __shfl_sync(FULLMASK, sdv, r * 4 + 0) + __shfl_sync(FULLMASK, arv, r * 4 + 0);
    float a1 = sv.y + __shfl_sync(FULLMASK, sdv, r * 4 + 1) + __shfl_sync(FULLMASK, arv, r * 4 + 1);
    float a2 = sv.z + __shfl_sync(FULLMASK, sdv, r * 4 + 2) + __shfl_sync(FULLMASK, arv, r * 4 + 2);
    float a3 = sv.w + __shfl_sync(FULLMASK, sdv, r * 4 + 3) + __shfl_sync(FULLMASK, arv, r * 4 + 3);
    a0 = a0 > 0.f ? a0 : 0.2f * a0;
    a1 = a1 > 0.f ? a1 : 0.2f * a1;
    a2 = a2 > 0.f ? a2 : 0.2f * a2;
    a3 = a3 > 0.f ? a3 : 0.2f * a3;
    float c0 = __expf(a0 - mx0) * iv0;
    float c1 = __expf(a1 - mx1) * iv1;
    float c2 = __expf(a2 - mx2) * iv2;
    float c3 = __expf(a3 - mx3) * iv3;
    float c = (h == 0) ? c0 : (h == 1) ? c1 : (h == 2) ? c2 : c3;
    const float* xp = g_xw + ((size_t)src * 8 + r) * 256 + lane * 8;
    float4 v0 = *(const float4*)xp;
    float4 v1 = *(const float4*)(xp + 4);
    acc0 = fmaf(c, v0.x, acc0); acc1 = fmaf(c, v0.y, acc1);
    acc2 = fmaf(c, v0.z, acc2); acc3 = fmaf(c, v0.w, acc3);
    acc4 = fmaf(c, v1.x, acc4); acc5 = fmaf(c, v1.y, acc5);
    acc6 = fmaf(c, v1.z, acc6); acc7 = fmaf(c, v1.w, acc7);
  }

  float4 b0 = *(const float4*)(bias + lane * 8);
  float4 b1 = *(const float4*)(bias + lane * 8 + 4);
  float w0 = acc0 + b0.x, w1 = acc1 + b0.y, w2 = acc2 + b0.z, w3 = acc3 + b0.w;
  float w4 = acc4 + b1.x, w5 = acc5 + b1.y, w6 = acc6 + b1.z, w7 = acc7 + b1.w;
  float s  = w0 + w1 + w2 + w3 + w4 + w5 + w6 + w7;
  float ss = w0 * w0 + w1 * w1 + w2 * w2 + w3 * w3 + w4 * w4 + w5 * w5 + w6 * w6 + w7 * w7;
#pragma unroll
  for (int off = 16; off; off >>= 1) {
    s  += __shfl_xor_sync(FULLMASK, s, off);
    ss += __shfl_xor_sync(FULLMASK, ss, off);
  }
  float mean = s * (1.f / 256.f);
  float var  = fmaxf(ss * (1.f / 256.f) - mean * mean, 0.f);
  float inv  = rsqrtf(var + 1e-5f);
  float4 gg0 = *(const float4*)(gam + lane * 8);
  float4 gg1 = *(const float4*)(gam + lane * 8 + 4);
  float4 bb0 = *(const float4*)(bet + lane * 8);
  float4 bb1 = *(const float4*)(bet + lane * 8 + 4);
  float o0 = (w0 - mean) * inv * gg0.x + bb0.x;
  float o1 = (w1 - mean) * inv * gg0.y + bb0.y;
  float o2 = (w2 - mean) * inv * gg0.z + bb0.z;
  float o3 = (w3 - mean) * inv * gg0.w + bb0.w;
  float o4 = (w4 - mean) * inv * gg1.x + bb1.x;
  float o5 = (w5 - mean) * inv * gg1.y + bb1.y;
  float o6 = (w6 - mean) * inv * gg1.z + bb1.z;
  float o7 = (w7 - mean) * inv * gg1.w + bb1.w;
  o0 = o0 > 0.f ? o0 : expm1f(o0);
  o1 = o1 > 0.f ? o1 : expm1f(o1);
  o2 = o2 > 0.f ? o2 : expm1f(o2);
  o3 = o3 > 0.f ? o3 : expm1f(o3);
  o4 = o4 > 0.f ? o4 : expm1f(o4);
  o5 = o5 > 0.f ? o5 : expm1f(o5);
  o6 = o6 > 0.f ? o6 : expm1f(o6);
  o7 = o7 > 0.f ? o7 : expm1f(o7);

  // fused split: write next layer's A directly as bf16 hi/lo (K=256 layout)
  size_t base = (size_t)i * 256 + lane * 8;
  __nv_bfloat16 h0, l0, h1, l1;
  split1(o0, h0, l0); split1(o1, h1, l1);
  *(__nv_bfloat162*)(g_ah + base)     = __nv_bfloat162(h0, h1);
  *(__nv_bfloat162*)(g_al + base)     = __nv_bfloat162(l0, l1);
  split1(o2, h0, l0); split1(o3, h1, l1);
  *(__nv_bfloat162*)(g_ah + base + 2) = __nv_bfloat162(h0, h1);
  *(__nv_bfloat162*)(g_al + base + 2) = __nv_bfloat162(l0, l1);
  split1(o4, h0, l0); split1(o5, h1, l1);
  *(__nv_bfloat162*)(g_ah + base + 4) = __nv_bfloat162(h0, h1);
  *(__nv_bfloat162*)(g_al + base + 4) = __nv_bfloat162(l0, l1);
  split1(o6, h0, l0); split1(o7, h1, l1);
  *(__nv_bfloat162*)(g_ah + base + 6) = __nv_bfloat162(h0, h1);
  *(__nv_bfloat162*)(g_al + base + 6) = __nv_bfloat162(l0, l1);
}

// ---------------- final layer: H=1, D=64, writes d_out ----------------------
__global__ __launch_bounds__(256) void k_agg1(const float* __restrict__ arel,
                                              const float* __restrict__ bias,
                                              float* __restrict__ out) {
  int wid = threadIdx.x >> 5, lane = threadIdx.x & 31;
  int i = blockIdx.x * 8 + wid;
  if (i >= NN) return;
  float sdv = (lane < 8) ? g_sdst[i * 8 + lane] : 0.f;
  float arv = (lane < 8) ? arel[lane] : 0.f;
  int begin = g_rowptr[i], end = g_rowptr[i + 1];
  int deg = end - begin;
  int nIt = (deg + 31) >> 5;

  float mx = -1e30f;
  for (int j = 0; j < nIt; j++) {
    int e = begin + j * 32 + lane;
    bool act = e < end;
    int pk = g_srt[act ? e : begin];
    int src = pk & 0xFFFFF, r = pk >> 20;
    float a = g_ssrc[(size_t)src * 8 + r] + __shfl_sync(FULLMASK, sdv, r) + __shfl_sync(FULLMASK, arv, r);
    a = a > 0.f ? a : 0.2f * a;
    if (act) mx = fmaxf(mx, a);
  }
#pragma unroll
  for (int off = 16; off; off >>= 1) mx = fmaxf(mx, __shfl_xor_sync(FULLMASK, mx, off));

  float dn = 0.f;
  for (int j = 0; j < nIt; j++) {
    int e = begin + j * 32 + lane;
    bool act = e < end;
    int pk = g_srt[act ? e : begin];
    int src = pk & 0xFFFFF, r = pk >> 20;
    float a = g_ssrc[(size_t)src * 8 + r] + __shfl_sync(FULLMASK, sdv, r) + __shfl_sync(FULLMASK, arv, r);
    a = a > 0.f ? a : 0.2f * a;
    if (act) dn += __expf(a - mx);
  }
#pragma unroll
  for (int off = 16; off; off >>= 1) dn += __shfl_xor_sync(FULLMASK, dn, off);
  float iv = 1.f / dn;

  float a0 = 0.f, a1 = 0.f;
  for (int e = begin; e < end; e++) {
    int pk = g_srt[e];
    int src = pk & 0xFFFFF, r = pk >> 20;
    float a = g_ssrc[(size_t)src * 8 + r] + __shfl_sync(FULLMASK, sdv, r) + __shfl_sync(FULLMASK, arv, r);
    a = a > 0.f ? a : 0.2f * a;
    float c = __expf(a - mx) * iv;
    float2 vv = *(const float2*)(g_xw + ((size_t)src * 8 + r) * 64 + lane * 2);
    a0 = fmaf(c, vv.x, a0);
    a1 = fmaf(c, vv.y, a1);
  }
  out[(size_t)i * 64 + lane * 2]     = a0 + bias[lane * 2];
  out[(size_t)i * 64 + lane * 2 + 1] = a1 + bias[lane * 2 + 1];
}

// ---------------- launch -----------------------------------------------------
extern "C" void kernel_launch(void* const* d_in, const int* in_sizes, int n_in,
                              void* d_out, int out_size) {
  const float* x   = (const float*)d_in[0];
  const void*  ei  = d_in[1];
  const void*  et  = d_in[2];
  const float* W0  = (const float*)d_in[3];
  const float* as0 = (const float*)d_in[4];
  const float* ad0 = (const float*)d_in[5];
  const float* ar0 = (const float*)d_in[6];
  const float* bi0 = (const float*)d_in[7];
  const float* W1  = (const float*)d_in[8];
  const float* as1 = (const float*)d_in[9];
  const float* ad1 = (const float*)d_in[10];
  const float* ar1 = (const float*)d_in[11];
  const float* bi1 = (const float*)d_in[12];
  const float* W2  = (const float*)d_in[13];
  const float* as2 = (const float*)d_in[14];
  const float* ad2 = (const float*)d_in[15];
  const float* ar2 = (const float*)d_in[16];
  const float* bi2 = (const float*)d_in[17];
  const float* g0  = (const float*)d_in[18];
  const float* be0 = (const float*)d_in[19];
  const float* g1  = (const float*)d_in[20];
  const float* be1 = (const float*)d_in[21];
  float* out = (float*)d_out;

  cudaFuncSetAttribute(k_gemm_v4, cudaFuncAttributeMaxDynamicSharedMemorySize, SM_TOTAL);

  // graph prep
  k_detect<<<1, 64>>>((const unsigned*)ei, (const unsigned*)et);
  k_zero_deg<<<(NN + 255) / 256, 256>>>();
  k_hist<<<(NE + 255) / 256, 256>>>(ei);
  const int NB = (NN + 1023) / 1024;  // 49
  k_bsum<<<NB, 1024>>>();
  k_bscan<<<1, 64>>>(NB);
  k_bwrite<<<NB, 1024>>>();
  k_scatter<<<(NE + 255) / 256, 256>>>(ei, et);

  const int MB = (NN + 127) / 128;  // 391
  const int NS4 = NN * NRR * 4, NS1 = NN * NRR;

  // layer 0: K=128, D=256, H=4
  k_split_a<<<(int)(((long long)NN * 128 / 4 + 255) / 256), 256>>>(x, 128);
  k_split_w<<<(int)((8LL * 128 * 256 + 255) / 256), 256>>>(W0, 8LL * 128 * 256);
  k_zero_s<<<(NS4 + 255) / 256, 256>>>(NS4);
  k_gemm_v4<<<dim3(MB, 4, 8), 256, SM_TOTAL>>>(128, 256, as0, ad0, 4);
  k_agg4<<<(NN + 7) / 8, 256>>>(ar0, bi0, g0, be0);

  // layer 1: K=256, D=256, H=4  (A split written by layer-0 agg epilogue)
  k_split_w<<<(int)((8LL * 256 * 256 + 255) / 256), 256>>>(W1, 8LL * 256 * 256);
  k_zero_s<<<(NS4 + 255) / 256, 256>>>(NS4);
  k_gemm_v4<<<dim3(MB, 4, 8), 256, SM_TOTAL>>>(256, 256, as1, ad1, 4);
  k_agg4<<<(NN + 7) / 8, 256>>>(ar1, bi1, g1, be1);

  // layer 2: K=256, D=64, H=1  (A split written by layer-1 agg epilogue)
  k_split_w<<<(int)((8LL * 256 * 64 + 255) / 256), 256>>>(W2, 8LL * 256 * 64);
  k_zero_s<<<(NS1 + 255) / 256, 256>>>(NS1);
  k_gemm_v4<<<dim3(MB, 1, 8), 256, SM_TOTAL>>>(256, 64, as2, ad2, 1);
  k_agg1<<<(NN + 7) / 8, 256>>>(ar2, bi2, out);
}